// round 13
// baseline (speedup 1.0000x reference)
#include <cuda_runtime.h>
#include <cuda_bf16.h>
#include <cuda_fp16.h>
#include <math.h>
#include <stdint.h>

// Problem constants
static constexpr int B_    = 32;
static constexpr int N_    = 2048;
static constexpr int D_    = 128;
static constexpr int HALF_ = 64;
static constexpr float DT_ = 0.01f;
static constexpr int M_ROWS = B_ * N_;   // 65536

// adj prescale (keeps fp16 adj values in normal range; descale in epilogue)
static constexpr float ADJ_S     = 256.0f;
static constexpr float ADJ_S_INV = 1.0f / 256.0f;

// Scratch (static device globals)
__device__ float         g_h  [M_ROWS * D_];      // h fp32 [B][N][D]
__device__ __nv_bfloat16 g_hb [M_ROWS * D_];      // bf16 mirror of h
__device__ __half        g_adjf[N_ * N_];         // adj fp16 (x256)
__device__ __half        g_gT [2 * N_ * N_];      // gT fp16 [b*128+d][node]
__device__ __half        g_xh [M_ROWS * 256];     // concat(x,hz) fp16
__device__ __half        g_af [M_ROWS * 256];     // relu hidden fp16
__device__ __half        g_WaT_h[256 * 256], g_WaT_l[256 * 256];
__device__ __half        g_WbT_h[128 * 256], g_WbT_l[128 * 256];
__device__ __nv_bfloat16 g_WcT[128 * 128];        // [d][k]: d<64->W1, d>=64->W2

__device__ __forceinline__ float4 ld4(const float* p) {
    return *reinterpret_cast<const float4*>(p);
}
__device__ __forceinline__ uint32_t s2u(const void* p) {
    uint32_t r;
    asm("{ .reg .u64 t; cvta.to.shared.u64 t, %1; cvt.u32.u64 %0, t; }"
        : "=r"(r) : "l"(p));
    return r;
}
__device__ __forceinline__ void cp16(uint32_t d, const void* s) {
    asm volatile("cp.async.cg.shared.global [%0], [%1], 16;" :: "r"(d), "l"(s) : "memory");
}
__device__ __forceinline__ uint32_t swz(uint32_t o)   { return o ^ ((o >> 3) & 0x70); }
__device__ __forceinline__ uint32_t swz64(uint32_t o) { return o ^ ((o >> 3) & 0x30); }
__device__ __forceinline__ float tanh_fast(float x) {
    float y;
    asm("tanh.approx.f32 %0, %1;" : "=f"(y) : "f"(x));
    return y;
}
__device__ __forceinline__ void ldsm4(uint32_t (&r)[4], uint32_t addr) {
    asm volatile("ldmatrix.sync.aligned.m8n8.x4.shared.b16 {%0,%1,%2,%3}, [%4];"
                 : "=r"(r[0]), "=r"(r[1]), "=r"(r[2]), "=r"(r[3]) : "r"(addr));
}
__device__ __forceinline__ void mma16816(float (&c)[4], const uint32_t (&a)[4],
                                         const uint32_t* b) {
    asm volatile(
        "mma.sync.aligned.m16n8k16.row.col.f32.bf16.bf16.f32 "
        "{%0,%1,%2,%3}, {%4,%5,%6,%7}, {%8,%9}, {%0,%1,%2,%3};"
        : "+f"(c[0]), "+f"(c[1]), "+f"(c[2]), "+f"(c[3])
        : "r"(a[0]), "r"(a[1]), "r"(a[2]), "r"(a[3]), "r"(b[0]), "r"(b[1]));
}
__device__ __forceinline__ void mma_f16(float (&c)[4], const uint32_t (&a)[4],
                                        const uint32_t* b) {
    asm volatile(
        "mma.sync.aligned.m16n8k16.row.col.f32.f16.f16.f32 "
        "{%0,%1,%2,%3}, {%4,%5,%6,%7}, {%8,%9}, {%0,%1,%2,%3};"
        : "+f"(c[0]), "+f"(c[1]), "+f"(c[2]), "+f"(c[3])
        : "r"(a[0]), "r"(a[1]), "r"(a[2]), "r"(a[3]), "r"(b[0]), "r"(b[1]));
}
// fp16-accumulate mma: D/C are 2 x f16x2 regs
__device__ __forceinline__ void mma_f16acc(uint32_t (&c)[2], const uint32_t (&a)[4],
                                           const uint32_t* b) {
    asm volatile(
        "mma.sync.aligned.m16n8k16.row.col.f16.f16.f16.f16 "
        "{%0,%1}, {%2,%3,%4,%5}, {%6,%7}, {%0,%1};"
        : "+r"(c[0]), "+r"(c[1])
        : "r"(a[0]), "r"(a[1]), "r"(a[2]), "r"(a[3]), "r"(b[0]), "r"(b[1]));
}
__device__ __forceinline__ void split2h(float v, __half& hi, __half& lo) {
    hi = __float2half_rn(v);
    lo = __float2half_rn(v - __half2float(hi));
}

// ===========================================================================
// Conversion kernels
// ===========================================================================
__global__ __launch_bounds__(256) void cvt_adj_k(const float* __restrict__ a)
{
    const int i = blockIdx.x * 256 + threadIdx.x;
    float4 v = ld4(a + (size_t)i * 4);
    *reinterpret_cast<__half2*>(g_adjf + (size_t)i * 4)     =
        __floats2half2_rn(v.x * ADJ_S, v.y * ADJ_S);
    *reinterpret_cast<__half2*>(g_adjf + (size_t)i * 4 + 2) =
        __floats2half2_rn(v.z * ADJ_S, v.w * ADJ_S);
}

__global__ __launch_bounds__(256) void cvt_xh_k(const float* __restrict__ x,
                                                const float* __restrict__ hz)
{
    const int i = blockIdx.x * 256 + threadIdx.x;
    const bool isHz = i >= 2097152;
    const int j = isHz ? i - 2097152 : i;
    const int row = j >> 5;
    const int c4  = (j & 31) * 4;
    float4 v = ld4((isHz ? hz : x) + (size_t)row * 128 + c4);
    const size_t o = (size_t)row * 256 + (isHz ? 128 : 0) + c4;
    *reinterpret_cast<__half2*>(g_xh + o)     = __floats2half2_rn(v.x, v.y);
    *reinterpret_cast<__half2*>(g_xh + o + 2) = __floats2half2_rn(v.z, v.w);
}

__global__ __launch_bounds__(256) void cvt_w_k(const float* __restrict__ Wa,
                                               const float* __restrict__ Wb,
                                               const float* __restrict__ W1,
                                               const float* __restrict__ W2)
{
    const int i = blockIdx.x * 256 + threadIdx.x;
    if (i < 65536) {
        const int n = i >> 8, k = i & 255;
        __half hi, lo;
        split2h(Wa[k * 256 + n], hi, lo);
        g_WaT_h[i] = hi; g_WaT_l[i] = lo;
    } else if (i < 65536 + 32768) {
        const int j = i - 65536;
        const int n = j >> 8, k = j & 255;
        __half hi, lo;
        split2h(Wb[k * 128 + n], hi, lo);
        g_WbT_h[j] = hi; g_WbT_l[j] = lo;
    } else if (i < 65536 + 32768 + 16384) {
        const int j = i - 98304;
        const int d = j >> 7, k = j & 127;
        const float w = (d < 64) ? W1[k * 128 + d] : W2[k * 128 + d];
        g_WcT[j] = __float2bfloat16(w);
    }
}

// ===========================================================================
// MLP GEMM (fp16 2-term split) — unchanged from R12.
// ===========================================================================
static constexpr int MLP_STG_B = 24576;
static constexpr int MLP_SMEM  = 3 * MLP_STG_B;   // 73728
static constexpr int MLP_NK    = 8;

template <int MODE>
__global__ __launch_bounds__(256, 2) void mlp_mma_k(
    const __half* __restrict__ A,
    const __half* __restrict__ Bh, const __half* __restrict__ Bl,
    const float* __restrict__ bias)
{
    extern __shared__ char smem[];
    const uint32_t sb = s2u(smem);
    const int tid  = threadIdx.x;
    const int lane = tid & 31;
    const int warp = tid >> 5;
    const int wm   = warp & 1;
    const int wn   = warp >> 1;
    const int bx = blockIdx.x;
    const int by = blockIdx.y;

    float acc[4][4][4];
#pragma unroll
    for (int i = 0; i < 4; i++)
#pragma unroll
        for (int j = 0; j < 4; j++)
#pragma unroll
            for (int v = 0; v < 4; v++) acc[i][j][v] = 0.0f;

    const int ldRow  = tid >> 1;
    const int ldHalf = tid & 1;

    auto issue = [&](int c, int s) {
        const uint32_t st = sb + s * MLP_STG_B;
        const size_t aOff = (size_t)(by * 128 + ldRow) * 256 + c * 32;
        const size_t bOff = (size_t)(bx * 128 + ldRow) * 256 + c * 32;
#pragma unroll
        for (int j = 0; j < 2; j++) {
            const int chunk = ldHalf * 2 + j;
            const uint32_t so = swz64((uint32_t)(ldRow * 64 + chunk * 16));
            const int e = chunk * 8;
            cp16(st + so,          A  + aOff + e);
            cp16(st + 8192 + so,   Bh + bOff + e);
            cp16(st + 16384 + so,  Bl + bOff + e);
        }
    };

    auto compute = [&](int s) {
        const uint32_t st = sb + s * MLP_STG_B;
#pragma unroll
        for (int ks = 0; ks < 2; ks++) {
            const int k0b = ks * 32;
            uint32_t ah[4][4];
#pragma unroll
            for (int mt = 0; mt < 4; mt++) {
                const int row = wm * 64 + mt * 16 + (lane & 15);
                const uint32_t o = swz64((uint32_t)(row * 64 + k0b + ((lane >> 4) << 4)));
                ldsm4(ah[mt], st + o);
            }
#pragma unroll
            for (int p = 0; p < 2; p++) {
                uint32_t bh[4], bl[4];
                const int row = wn * 32 + p * 16 + (lane & 7) + ((lane >> 4) << 3);
                const uint32_t o = swz64((uint32_t)(row * 64 + k0b + (((lane >> 3) & 1) << 4)));
                ldsm4(bh, st + 8192 + o);
                ldsm4(bl, st + 16384 + o);
#pragma unroll
                for (int mt = 0; mt < 4; mt++)
#pragma unroll
                    for (int sub = 0; sub < 2; sub++) {
                        const int nt = p * 2 + sub;
                        mma_f16(acc[mt][nt], ah[mt], &bh[sub * 2]);
                        mma_f16(acc[mt][nt], ah[mt], &bl[sub * 2]);
                    }
            }
        }
    };

    issue(0, 0);
    asm volatile("cp.async.commit_group;" ::: "memory");
    issue(1, 1);
    asm volatile("cp.async.commit_group;" ::: "memory");
    for (int kt = 0; kt < MLP_NK; kt++) {
        asm volatile("cp.async.wait_group 1;" ::: "memory");
        __syncthreads();
        compute(kt % 3);
        if (kt + 2 < MLP_NK) issue(kt + 2, (kt + 2) % 3);
        asm volatile("cp.async.commit_group;" ::: "memory");
    }

#pragma unroll
    for (int mt = 0; mt < 4; mt++) {
        const int row0 = by * 128 + wm * 64 + mt * 16 + (lane >> 2);
#pragma unroll
        for (int nt = 0; nt < 4; nt++) {
            const int col = bx * 128 + wn * 32 + nt * 8 + 2 * (lane & 3);
            const float b0 = bias[col], b1 = bias[col + 1];
#pragma unroll
            for (int r = 0; r < 2; r++) {
                const int row = row0 + r * 8;
                float v0 = acc[mt][nt][2 * r + 0] + b0;
                float v1 = acc[mt][nt][2 * r + 1] + b1;
                if (MODE == 1) {
                    v0 = fmaxf(v0, 0.0f);
                    v1 = fmaxf(v1, 0.0f);
                    const size_t o = (size_t)row * 256 + col;
                    *reinterpret_cast<__half2*>(g_af + o) = __floats2half2_rn(v0, v1);
                } else {
                    v0 = tanhf(v0);
                    v1 = tanhf(v1);
                    const size_t o = (size_t)row * 128 + col;
                    *reinterpret_cast<float2*>(g_h + o) = make_float2(v0, v1);
                    *reinterpret_cast<__nv_bfloat162*>(g_hb + o) =
                        __floats2bfloat162_rn(v0, v1);
                }
            }
        }
    }
}

// ===========================================================================
// gproj (bf16 mma, merged): g = hb @ WcT^T (128 cols), epilogue emits fp16
// transposed into gT[b*128+d][node]. CTA 128x128, K=128, 2 CTAs/SM.
// ===========================================================================
static constexpr int GP_SMEM = 65536 + 128 * 132 * 2;   // 99328

__global__ __launch_bounds__(256, 2) void gproj_k(__half* __restrict__ gT)
{
    extern __shared__ char smem[];
    const uint32_t sb = s2u(smem);
    unsigned short* Ts = reinterpret_cast<unsigned short*>(smem + 65536);
    const int tid  = threadIdx.x;
    const int lane = tid & 31;
    const int warp = tid >> 5;
    const int wm   = warp & 1;
    const int wn   = warp >> 1;
    const int by = blockIdx.y;

    {
        const int r = tid >> 1, half = tid & 1;
        const size_t aOff = (size_t)(by * 128 + r) * 128;
        const size_t bOff = (size_t)r * 128;
#pragma unroll
        for (int c = 0; c < 2; c++)
#pragma unroll
            for (int j = 0; j < 4; j++) {
                const uint32_t so = swz((uint32_t)(r * 128 + (half * 4 + j) * 16));
                const int e = c * 64 + (half * 4 + j) * 8;
                cp16(sb + c * 16384 + so,         g_hb  + aOff + e);
                cp16(sb + 32768 + c * 16384 + so, g_WcT + bOff + e);
            }
    }
    asm volatile("cp.async.commit_group;" ::: "memory");
    asm volatile("cp.async.wait_group 0;" ::: "memory");
    __syncthreads();

    float acc[4][4][4];
#pragma unroll
    for (int i = 0; i < 4; i++)
#pragma unroll
        for (int j = 0; j < 4; j++)
#pragma unroll
            for (int v = 0; v < 4; v++) acc[i][j][v] = 0.0f;

#pragma unroll
    for (int c = 0; c < 2; c++) {
        const uint32_t aB = sb + c * 16384;
        const uint32_t bB = sb + 32768 + c * 16384;
#pragma unroll
        for (int ks = 0; ks < 4; ks++) {
            const int k0b = ks * 32;
            uint32_t af[4][4], bf[2][4];
#pragma unroll
            for (int mt = 0; mt < 4; mt++) {
                const int row = wm * 64 + mt * 16 + (lane & 15);
                ldsm4(af[mt], aB + swz((uint32_t)(row * 128 + k0b + ((lane >> 4) << 4))));
            }
#pragma unroll
            for (int p = 0; p < 2; p++) {
                const int row = wn * 32 + p * 16 + (lane & 7) + ((lane >> 4) << 3);
                ldsm4(bf[p], bB + swz((uint32_t)(row * 128 + k0b + (((lane >> 3) & 1) << 4))));
            }
#pragma unroll
            for (int mt = 0; mt < 4; mt++)
#pragma unroll
                for (int nt = 0; nt < 4; nt++)
                    mma16816(acc[mt][nt], af[mt], &bf[nt >> 1][(nt & 1) * 2]);
        }
    }
    __syncthreads();

    // stage fp16 then transposed coalesced store
#pragma unroll
    for (int mt = 0; mt < 4; mt++) {
        const int row0 = wm * 64 + mt * 16 + (lane >> 2);
#pragma unroll
        for (int nt = 0; nt < 4; nt++) {
            const int col = wn * 32 + nt * 8 + 2 * (lane & 3);
#pragma unroll
            for (int r = 0; r < 2; r++) {
                const int row = row0 + r * 8;
                __half b0 = __float2half_rn(acc[mt][nt][2 * r + 0]);
                __half b1 = __float2half_rn(acc[mt][nt][2 * r + 1]);
                Ts[row * 132 + col]     = *reinterpret_cast<unsigned short*>(&b0);
                Ts[row * 132 + col + 1] = *reinterpret_cast<unsigned short*>(&b1);
            }
        }
    }
    __syncthreads();

    const int colp = tid & 127;
    const int seg  = tid >> 7;
    const int b    = by >> 4;
    const int n0   = (by & 15) * 128;
    __half* dst = gT + (size_t)(b * 128 + colp) * N_ + n0 + seg * 64;
#pragma unroll
    for (int q = 0; q < 8; q++) {
        const int r0 = seg * 64 + q * 8;
        uint32_t w[4];
#pragma unroll
        for (int p = 0; p < 4; p++) {
            uint32_t lo = Ts[(r0 + 2 * p) * 132 + colp];
            uint32_t hi = Ts[(r0 + 2 * p + 1) * 132 + colp];
            w[p] = lo | (hi << 16);
        }
        *reinterpret_cast<uint4*>(dst + q * 8) = make_uint4(w[0], w[1], w[2], w[3]);
    }
}

// ===========================================================================
// adj GEMM (fp16 mma, FP16 ACCUMULATE) + full h-update epilogue.
// A = adjf (fp16, x256), B = gT (fp16). Descale x(1/256) in epilogue.
// CTA 128x128, BK=64, 3-stage cp.async (96 KB), 2 CTAs/SM. Grid (32,16).
// ===========================================================================
static constexpr int AJ_STAGES  = 3;
static constexpr int AJ_NK      = N_ / 64;         // 32
static constexpr int AJ_TILE    = 16384;
static constexpr int AJ_STAGE_B = 2 * AJ_TILE;
static constexpr int ADJ_SMEM   = AJ_STAGES * AJ_STAGE_B;   // 96 KB

template <bool WOUT, bool WH>
__global__ __launch_bounds__(256, 2) void adj_mma_k(
    float* __restrict__ out, const float* __restrict__ eps)
{
    extern __shared__ char smem[];
    const uint32_t sb = s2u(smem);
    const int tid  = threadIdx.x;
    const int lane = tid & 31;
    const int warp = tid >> 5;
    const int wm   = warp & 1;
    const int wn   = warp >> 1;
    const int bx = blockIdx.x;      // b (0..31)
    const int by = blockIdx.y;      // node tile

    const char* aSrc = (const char*)(g_adjf + (size_t)(by * 128) * N_);
    const char* bSrc = (const char*)(g_gT   + (size_t)(bx * 128) * N_);

    uint32_t acc[4][4][2];          // fp16x2 accumulators
#pragma unroll
    for (int i = 0; i < 4; i++)
#pragma unroll
        for (int j = 0; j < 4; j++) { acc[i][j][0] = 0u; acc[i][j][1] = 0u; }

    const int ldRow = tid >> 3;
    const int ldCol = tid & 7;

    auto issue = [&](int kt, int s) {
        const uint32_t aB = sb + s * AJ_STAGE_B;
        const uint32_t bB = aB + AJ_TILE;
#pragma unroll
        for (int i = 0; i < 4; i++) {
            const int row = ldRow + 32 * i;
            const uint32_t so = swz((uint32_t)(row * 128 + ldCol * 16));
            const size_t gsrc = (size_t)row * (N_ * 2) + kt * 128 + ldCol * 16;
            cp16(aB + so, aSrc + gsrc);
            cp16(bB + so, bSrc + gsrc);
        }
    };

    auto compute = [&](int s) {
        const uint32_t aB = sb + s * AJ_STAGE_B;
        const uint32_t bB = aB + AJ_TILE;
#pragma unroll
        for (int ks = 0; ks < 4; ks++) {
            const int k0b = ks * 32;
            uint32_t af[4][4], bf[2][4];
#pragma unroll
            for (int mt = 0; mt < 4; mt++) {
                const int row = wm * 64 + mt * 16 + (lane & 15);
                ldsm4(af[mt], aB + swz((uint32_t)(row * 128 + k0b + ((lane >> 4) << 4))));
            }
#pragma unroll
            for (int p = 0; p < 2; p++) {
                const int row = wn * 32 + p * 16 + (lane & 7) + ((lane >> 4) << 3);
                ldsm4(bf[p], bB + swz((uint32_t)(row * 128 + k0b + (((lane >> 3) & 1) << 4))));
            }
#pragma unroll
            for (int mt = 0; mt < 4; mt++)
#pragma unroll
                for (int nt = 0; nt < 4; nt++)
                    mma_f16acc(acc[mt][nt], af[mt], &bf[nt >> 1][(nt & 1) * 2]);
        }
    };

    issue(0, 0);
    asm volatile("cp.async.commit_group;" ::: "memory");
    issue(1, 1);
    asm volatile("cp.async.commit_group;" ::: "memory");
    for (int kt = 0; kt < AJ_NK; kt++) {
        asm volatile("cp.async.wait_group 1;" ::: "memory");
        __syncthreads();
        compute(kt % 3);
        const int f = kt + 2;
        if (f < AJ_NK) issue(f, f % 3);
        asm volatile("cp.async.commit_group;" ::: "memory");
    }

    // fused epilogue: full h update (both halves), descale x(1/256)
    const bool secondHalf = (wn >= 2);
#pragma unroll
    for (int mt = 0; mt < 4; mt++) {
        const int node0 = by * 128 + wm * 64 + mt * 16 + (lane >> 2);
#pragma unroll
        for (int nt = 0; nt < 4; nt++) {
            const int d = wn * 32 + nt * 8 + 2 * (lane & 3);
#pragma unroll
            for (int r = 0; r < 2; r++) {
                const int node = node0 + r * 8;
                const float2 tp = __half22float2(
                    *reinterpret_cast<const __half2*>(&acc[mt][nt][r]));
                const float t0 = tp.x * ADJ_S_INV;
                const float t1 = tp.y * ADJ_S_INV;
                const size_t bn = (size_t)bx * N_ + node;
                const size_t hi = bn * D_ + d;
                float2 hv = *reinterpret_cast<const float2*>(g_h + hi);
                if (!secondHalf) {
                    hv.x += DT_ * tanh_fast(t0);
                    hv.y += DT_ * tanh_fast(t1);
                } else {
                    float2 ev = *reinterpret_cast<const float2*>(
                        eps + bn * HALF_ + (d - HALF_));
                    ev.x = fminf(fmaxf(ev.x, 0.0f), 0.1f);
                    ev.y = fminf(fmaxf(ev.y, 0.0f), 0.1f);
                    hv.x = ev.x * (hv.x + DT_ * tanh_fast(t0));
                    hv.y = ev.y * (hv.y + DT_ * tanh_fast(t1));
                }
                if (WH) {
                    *reinterpret_cast<float2*>(g_h + hi) = hv;
                    *reinterpret_cast<__nv_bfloat162*>(g_hb + hi) =
                        __floats2bfloat162_rn(hv.x, hv.y);
                }
                if (WOUT)
                    *reinterpret_cast<float2*>(out + hi) = hv;
            }
        }
    }
}

// ===========================================================================
extern "C" void kernel_launch(void* const* d_in, const int* /*in_sizes*/,
                              int /*n_in*/, void* d_out, int /*out_size*/)
{
    const float* x   = (const float*)d_in[0];
    const float* hz  = (const float*)d_in[1];
    const float* adj = (const float*)d_in[2];
    const float* W1  = (const float*)d_in[3];
    const float* W2  = (const float*)d_in[4];
    const float* Wa  = (const float*)d_in[5];
    const float* ba  = (const float*)d_in[6];
    const float* Wb  = (const float*)d_in[7];
    const float* bb  = (const float*)d_in[8];
    const float* eps = (const float*)d_in[9];
    float* out = (float*)d_out;

    __half *xh_p, *af_p, *WaT_h, *WaT_l, *WbT_h, *WbT_l, *gT_p;
    cudaGetSymbolAddress((void**)&xh_p, g_xh);
    cudaGetSymbolAddress((void**)&af_p, g_af);
    cudaGetSymbolAddress((void**)&WaT_h, g_WaT_h);
    cudaGetSymbolAddress((void**)&WaT_l, g_WaT_l);
    cudaGetSymbolAddress((void**)&WbT_h, g_WbT_h);
    cudaGetSymbolAddress((void**)&WbT_l, g_WbT_l);
    cudaGetSymbolAddress((void**)&gT_p, g_gT);

    cudaFuncSetAttribute(mlp_mma_k<1>,
                         cudaFuncAttributeMaxDynamicSharedMemorySize, MLP_SMEM);
    cudaFuncSetAttribute(mlp_mma_k<2>,
                         cudaFuncAttributeMaxDynamicSharedMemorySize, MLP_SMEM);
    cudaFuncSetAttribute(gproj_k,
                         cudaFuncAttributeMaxDynamicSharedMemorySize, GP_SMEM);
    cudaFuncSetAttribute((const void*)adj_mma_k<false, true>,
                         cudaFuncAttributeMaxDynamicSharedMemorySize, ADJ_SMEM);
    cudaFuncSetAttribute((const void*)adj_mma_k<true, false>,
                         cudaFuncAttributeMaxDynamicSharedMemorySize, ADJ_SMEM);

    const dim3 blk(256);
    const dim3 adjGrid(2 * N_ / 128, N_ / 128);   // 32 x 16

    cvt_adj_k<<<(N_ * N_) / 1024, blk>>>(adj);
    cvt_xh_k<<<16384, blk>>>(x, hz);
    cvt_w_k<<<448, blk>>>(Wa, Wb, W1, W2);

    mlp_mma_k<1><<<dim3(2, M_ROWS / 128), blk, MLP_SMEM>>>(xh_p, WaT_h, WaT_l, ba);
    mlp_mma_k<2><<<dim3(1, M_ROWS / 128), blk, MLP_SMEM>>>(af_p, WbT_h, WbT_l, bb);

    // iteration 0: out writes skipped (overwritten by iteration 1)
    gproj_k<<<dim3(1, M_ROWS / 128), blk, GP_SMEM>>>(gT_p);
    adj_mma_k<false, true><<<adjGrid, blk, ADJ_SMEM>>>(out, eps);

    // iteration 1: write out; skip dead h/hb stores
    gproj_k<<<dim3(1, M_ROWS / 128), blk, GP_SMEM>>>(gT_p);
    adj_mma_k<true, false><<<adjGrid, blk, ADJ_SMEM>>>(out, eps);
}

// round 14
// speedup vs baseline: 1.0659x; 1.0659x over previous
#include <cuda_runtime.h>
#include <cuda_bf16.h>
#include <cuda_fp16.h>
#include <math.h>
#include <stdint.h>

// Problem constants
static constexpr int B_    = 32;
static constexpr int N_    = 2048;
static constexpr int D_    = 128;
static constexpr int HALF_ = 64;
static constexpr float DT_ = 0.01f;
static constexpr int M_ROWS = B_ * N_;   // 65536

// Scratch (static device globals)
__device__ float         g_h  [M_ROWS * D_];      // h fp32 [B][N][D]
__device__ __nv_bfloat16 g_hb [M_ROWS * D_];      // bf16 mirror of h
__device__ __nv_bfloat16 g_adjb[N_ * N_];         // adj bf16
__device__ __nv_bfloat16 g_gT [2 * N_ * N_];      // gT [b*128+d][node] (4096x2048)
__device__ __half        g_xh [M_ROWS * 256];     // concat(x,hz) fp16
__device__ __half        g_af [M_ROWS * 256];     // relu hidden fp16
__device__ __half        g_WaT_h[256 * 256], g_WaT_l[256 * 256];
__device__ __half        g_WbT_h[128 * 256], g_WbT_l[128 * 256];
__device__ __nv_bfloat16 g_WcT[128 * 128];        // [d][k]: d<64->W1, d>=64->W2

__device__ __forceinline__ float4 ld4(const float* p) {
    return *reinterpret_cast<const float4*>(p);
}
__device__ __forceinline__ uint32_t s2u(const void* p) {
    uint32_t r;
    asm("{ .reg .u64 t; cvta.to.shared.u64 t, %1; cvt.u32.u64 %0, t; }"
        : "=r"(r) : "l"(p));
    return r;
}
__device__ __forceinline__ void cp16(uint32_t d, const void* s) {
    asm volatile("cp.async.cg.shared.global [%0], [%1], 16;" :: "r"(d), "l"(s) : "memory");
}
__device__ __forceinline__ uint32_t swz(uint32_t o)   { return o ^ ((o >> 3) & 0x70); }
__device__ __forceinline__ uint32_t swz64(uint32_t o) { return o ^ ((o >> 3) & 0x30); }
__device__ __forceinline__ float tanh_fast(float x) {
    float y;
    asm("tanh.approx.f32 %0, %1;" : "=f"(y) : "f"(x));
    return y;
}
__device__ __forceinline__ void ldsm4(uint32_t (&r)[4], uint32_t addr) {
    asm volatile("ldmatrix.sync.aligned.m8n8.x4.shared.b16 {%0,%1,%2,%3}, [%4];"
                 : "=r"(r[0]), "=r"(r[1]), "=r"(r[2]), "=r"(r[3]) : "r"(addr));
}
__device__ __forceinline__ void mma16816(float (&c)[4], const uint32_t (&a)[4],
                                         const uint32_t* b) {
    asm volatile(
        "mma.sync.aligned.m16n8k16.row.col.f32.bf16.bf16.f32 "
        "{%0,%1,%2,%3}, {%4,%5,%6,%7}, {%8,%9}, {%0,%1,%2,%3};"
        : "+f"(c[0]), "+f"(c[1]), "+f"(c[2]), "+f"(c[3])
        : "r"(a[0]), "r"(a[1]), "r"(a[2]), "r"(a[3]), "r"(b[0]), "r"(b[1]));
}
__device__ __forceinline__ void mma_f16(float (&c)[4], const uint32_t (&a)[4],
                                        const uint32_t* b) {
    asm volatile(
        "mma.sync.aligned.m16n8k16.row.col.f32.f16.f16.f32 "
        "{%0,%1,%2,%3}, {%4,%5,%6,%7}, {%8,%9}, {%0,%1,%2,%3};"
        : "+f"(c[0]), "+f"(c[1]), "+f"(c[2]), "+f"(c[3])
        : "r"(a[0]), "r"(a[1]), "r"(a[2]), "r"(a[3]), "r"(b[0]), "r"(b[1]));
}
__device__ __forceinline__ void split2h(float v, __half& hi, __half& lo) {
    hi = __float2half_rn(v);
    lo = __float2half_rn(v - __half2float(hi));
}

// ===========================================================================
// Merged conversion kernel (one launch):
//   [0, 4194304)            : xh   (x / hz -> fp16, one float4 each)
//   [4194304, 5242880)      : adj  (fp32 -> bf16, one float4 each)
//   [5242880, 5357568)      : weights (Wa/Wb split-fp16, Wc bf16)
// ===========================================================================
static constexpr int CVT_XH_N  = 4194304;
static constexpr int CVT_ADJ_N = 1048576;
static constexpr int CVT_W_N   = 114688;
static constexpr int CVT_TOTAL = CVT_XH_N + CVT_ADJ_N + CVT_W_N;  // 5357568
static constexpr int CVT_BLOCKS = CVT_TOTAL / 256;                 // 20928

__global__ __launch_bounds__(256) void cvt_all_k(
    const float* __restrict__ x,  const float* __restrict__ hz,
    const float* __restrict__ adj,
    const float* __restrict__ Wa, const float* __restrict__ Wb,
    const float* __restrict__ W1, const float* __restrict__ W2)
{
    const int gi = blockIdx.x * 256 + threadIdx.x;
    if (gi < CVT_XH_N) {
        const bool isHz = gi >= (CVT_XH_N / 2);
        const int j = isHz ? gi - CVT_XH_N / 2 : gi;
        const int row = j >> 5;
        const int c4  = (j & 31) * 4;
        float4 v = ld4((isHz ? hz : x) + (size_t)row * 128 + c4);
        const size_t o = (size_t)row * 256 + (isHz ? 128 : 0) + c4;
        *reinterpret_cast<__half2*>(g_xh + o)     = __floats2half2_rn(v.x, v.y);
        *reinterpret_cast<__half2*>(g_xh + o + 2) = __floats2half2_rn(v.z, v.w);
    } else if (gi < CVT_XH_N + CVT_ADJ_N) {
        const int i = gi - CVT_XH_N;
        float4 v = ld4(adj + (size_t)i * 4);
        *reinterpret_cast<__nv_bfloat162*>(g_adjb + (size_t)i * 4)     =
            __floats2bfloat162_rn(v.x, v.y);
        *reinterpret_cast<__nv_bfloat162*>(g_adjb + (size_t)i * 4 + 2) =
            __floats2bfloat162_rn(v.z, v.w);
    } else {
        const int i = gi - CVT_XH_N - CVT_ADJ_N;
        if (i < 65536) {
            const int n = i >> 8, k = i & 255;
            __half hi, lo;
            split2h(Wa[k * 256 + n], hi, lo);
            g_WaT_h[i] = hi; g_WaT_l[i] = lo;
        } else if (i < 65536 + 32768) {
            const int j = i - 65536;
            const int n = j >> 8, k = j & 255;
            __half hi, lo;
            split2h(Wb[k * 128 + n], hi, lo);
            g_WbT_h[j] = hi; g_WbT_l[j] = lo;
        } else {
            const int j = i - 98304;
            const int d = j >> 7, k = j & 127;
            const float w = (d < 64) ? W1[k * 128 + d] : W2[k * 128 + d];
            g_WcT[j] = __float2bfloat16(w);
        }
    }
}

// ===========================================================================
// MLP GEMM (fp16 2-term split) — unchanged from R12.
// ===========================================================================
static constexpr int MLP_STG_B = 24576;
static constexpr int MLP_SMEM  = 3 * MLP_STG_B;   // 73728
static constexpr int MLP_NK    = 8;

template <int MODE>
__global__ __launch_bounds__(256, 2) void mlp_mma_k(
    const __half* __restrict__ A,
    const __half* __restrict__ Bh, const __half* __restrict__ Bl,
    const float* __restrict__ bias)
{
    extern __shared__ char smem[];
    const uint32_t sb = s2u(smem);
    const int tid  = threadIdx.x;
    const int lane = tid & 31;
    const int warp = tid >> 5;
    const int wm   = warp & 1;
    const int wn   = warp >> 1;
    const int bx = blockIdx.x;
    const int by = blockIdx.y;

    float acc[4][4][4];
#pragma unroll
    for (int i = 0; i < 4; i++)
#pragma unroll
        for (int j = 0; j < 4; j++)
#pragma unroll
            for (int v = 0; v < 4; v++) acc[i][j][v] = 0.0f;

    const int ldRow  = tid >> 1;
    const int ldHalf = tid & 1;

    auto issue = [&](int c, int s) {
        const uint32_t st = sb + s * MLP_STG_B;
        const size_t aOff = (size_t)(by * 128 + ldRow) * 256 + c * 32;
        const size_t bOff = (size_t)(bx * 128 + ldRow) * 256 + c * 32;
#pragma unroll
        for (int j = 0; j < 2; j++) {
            const int chunk = ldHalf * 2 + j;
            const uint32_t so = swz64((uint32_t)(ldRow * 64 + chunk * 16));
            const int e = chunk * 8;
            cp16(st + so,          A  + aOff + e);
            cp16(st + 8192 + so,   Bh + bOff + e);
            cp16(st + 16384 + so,  Bl + bOff + e);
        }
    };

    auto compute = [&](int s) {
        const uint32_t st = sb + s * MLP_STG_B;
#pragma unroll
        for (int ks = 0; ks < 2; ks++) {
            const int k0b = ks * 32;
            uint32_t ah[4][4];
#pragma unroll
            for (int mt = 0; mt < 4; mt++) {
                const int row = wm * 64 + mt * 16 + (lane & 15);
                const uint32_t o = swz64((uint32_t)(row * 64 + k0b + ((lane >> 4) << 4)));
                ldsm4(ah[mt], st + o);
            }
#pragma unroll
            for (int p = 0; p < 2; p++) {
                uint32_t bh[4], bl[4];
                const int row = wn * 32 + p * 16 + (lane & 7) + ((lane >> 4) << 3);
                const uint32_t o = swz64((uint32_t)(row * 64 + k0b + (((lane >> 3) & 1) << 4)));
                ldsm4(bh, st + 8192 + o);
                ldsm4(bl, st + 16384 + o);
#pragma unroll
                for (int mt = 0; mt < 4; mt++)
#pragma unroll
                    for (int sub = 0; sub < 2; sub++) {
                        const int nt = p * 2 + sub;
                        mma_f16(acc[mt][nt], ah[mt], &bh[sub * 2]);
                        mma_f16(acc[mt][nt], ah[mt], &bl[sub * 2]);
                    }
            }
        }
    };

    issue(0, 0);
    asm volatile("cp.async.commit_group;" ::: "memory");
    issue(1, 1);
    asm volatile("cp.async.commit_group;" ::: "memory");
    for (int kt = 0; kt < MLP_NK; kt++) {
        asm volatile("cp.async.wait_group 1;" ::: "memory");
        __syncthreads();
        compute(kt % 3);
        if (kt + 2 < MLP_NK) issue(kt + 2, (kt + 2) % 3);
        asm volatile("cp.async.commit_group;" ::: "memory");
    }

#pragma unroll
    for (int mt = 0; mt < 4; mt++) {
        const int row0 = by * 128 + wm * 64 + mt * 16 + (lane >> 2);
#pragma unroll
        for (int nt = 0; nt < 4; nt++) {
            const int col = bx * 128 + wn * 32 + nt * 8 + 2 * (lane & 3);
            const float b0 = bias[col], b1 = bias[col + 1];
#pragma unroll
            for (int r = 0; r < 2; r++) {
                const int row = row0 + r * 8;
                float v0 = acc[mt][nt][2 * r + 0] + b0;
                float v1 = acc[mt][nt][2 * r + 1] + b1;
                if (MODE == 1) {
                    v0 = fmaxf(v0, 0.0f);
                    v1 = fmaxf(v1, 0.0f);
                    const size_t o = (size_t)row * 256 + col;
                    *reinterpret_cast<__half2*>(g_af + o) = __floats2half2_rn(v0, v1);
                } else {
                    v0 = tanhf(v0);
                    v1 = tanhf(v1);
                    const size_t o = (size_t)row * 128 + col;
                    *reinterpret_cast<float2*>(g_h + o) = make_float2(v0, v1);
                    *reinterpret_cast<__nv_bfloat162*>(g_hb + o) =
                        __floats2bfloat162_rn(v0, v1);
                }
            }
        }
    }
}

// ===========================================================================
// gproj (bf16 mma, merged): g = hb @ WcT^T (128 cols), bf16 transposed into
// gT[b*128+d][node]. CTA 128x128, K=128, 2 CTAs/SM.
// ===========================================================================
static constexpr int GP_SMEM = 65536 + 128 * 132 * 2;   // 99328

__global__ __launch_bounds__(256, 2) void gproj_k(__nv_bfloat16* __restrict__ gT)
{
    extern __shared__ char smem[];
    const uint32_t sb = s2u(smem);
    unsigned short* Ts = reinterpret_cast<unsigned short*>(smem + 65536);
    const int tid  = threadIdx.x;
    const int lane = tid & 31;
    const int warp = tid >> 5;
    const int wm   = warp & 1;
    const int wn   = warp >> 1;
    const int by = blockIdx.y;

    {
        const int r = tid >> 1, half = tid & 1;
        const size_t aOff = (size_t)(by * 128 + r) * 128;
        const size_t bOff = (size_t)r * 128;
#pragma unroll
        for (int c = 0; c < 2; c++)
#pragma unroll
            for (int j = 0; j < 4; j++) {
                const uint32_t so = swz((uint32_t)(r * 128 + (half * 4 + j) * 16));
                const int e = c * 64 + (half * 4 + j) * 8;
                cp16(sb + c * 16384 + so,         g_hb  + aOff + e);
                cp16(sb + 32768 + c * 16384 + so, g_WcT + bOff + e);
            }
    }
    asm volatile("cp.async.commit_group;" ::: "memory");
    asm volatile("cp.async.wait_group 0;" ::: "memory");
    __syncthreads();

    float acc[4][4][4];
#pragma unroll
    for (int i = 0; i < 4; i++)
#pragma unroll
        for (int j = 0; j < 4; j++)
#pragma unroll
            for (int v = 0; v < 4; v++) acc[i][j][v] = 0.0f;

#pragma unroll
    for (int c = 0; c < 2; c++) {
        const uint32_t aB = sb + c * 16384;
        const uint32_t bB = sb + 32768 + c * 16384;
#pragma unroll
        for (int ks = 0; ks < 4; ks++) {
            const int k0b = ks * 32;
            uint32_t af[4][4], bf[2][4];
#pragma unroll
            for (int mt = 0; mt < 4; mt++) {
                const int row = wm * 64 + mt * 16 + (lane & 15);
                ldsm4(af[mt], aB + swz((uint32_t)(row * 128 + k0b + ((lane >> 4) << 4))));
            }
#pragma unroll
            for (int p = 0; p < 2; p++) {
                const int row = wn * 32 + p * 16 + (lane & 7) + ((lane >> 4) << 3);
                ldsm4(bf[p], bB + swz((uint32_t)(row * 128 + k0b + (((lane >> 3) & 1) << 4))));
            }
#pragma unroll
            for (int mt = 0; mt < 4; mt++)
#pragma unroll
                for (int nt = 0; nt < 4; nt++)
                    mma16816(acc[mt][nt], af[mt], &bf[nt >> 1][(nt & 1) * 2]);
        }
    }
    __syncthreads();

#pragma unroll
    for (int mt = 0; mt < 4; mt++) {
        const int row0 = wm * 64 + mt * 16 + (lane >> 2);
#pragma unroll
        for (int nt = 0; nt < 4; nt++) {
            const int col = wn * 32 + nt * 8 + 2 * (lane & 3);
#pragma unroll
            for (int r = 0; r < 2; r++) {
                const int row = row0 + r * 8;
                __nv_bfloat16 b0 = __float2bfloat16(acc[mt][nt][2 * r + 0]);
                __nv_bfloat16 b1 = __float2bfloat16(acc[mt][nt][2 * r + 1]);
                Ts[row * 132 + col]     = *reinterpret_cast<unsigned short*>(&b0);
                Ts[row * 132 + col + 1] = *reinterpret_cast<unsigned short*>(&b1);
            }
        }
    }
    __syncthreads();

    const int colp = tid & 127;
    const int seg  = tid >> 7;
    const int b    = by >> 4;
    const int n0   = (by & 15) * 128;
    __nv_bfloat16* dst = gT + (size_t)(b * 128 + colp) * N_ + n0 + seg * 64;
#pragma unroll
    for (int q = 0; q < 8; q++) {
        const int r0 = seg * 64 + q * 8;
        uint32_t w[4];
#pragma unroll
        for (int p = 0; p < 4; p++) {
            uint32_t lo = Ts[(r0 + 2 * p) * 132 + colp];
            uint32_t hi = Ts[(r0 + 2 * p + 1) * 132 + colp];
            w[p] = lo | (hi << 16);
        }
        *reinterpret_cast<uint4*>(dst + q * 8) = make_uint4(w[0], w[1], w[2], w[3]);
    }
}

// ===========================================================================
// adj GEMM (bf16 mma, f32 acc — R12 validated path) + full h-update epilogue.
// CTA 128x128, BK=64, 3-stage cp.async (96 KB), 2 CTAs/SM. Grid (32,16).
// ===========================================================================
static constexpr int AJ_STAGES  = 3;
static constexpr int AJ_NK      = N_ / 64;         // 32
static constexpr int AJ_TILE    = 16384;
static constexpr int AJ_STAGE_B = 2 * AJ_TILE;
static constexpr int ADJ_SMEM   = AJ_STAGES * AJ_STAGE_B;   // 96 KB

template <bool WOUT, bool WH>
__global__ __launch_bounds__(256, 2) void adj_mma_k(
    float* __restrict__ out, const float* __restrict__ eps)
{
    extern __shared__ char smem[];
    const uint32_t sb = s2u(smem);
    const int tid  = threadIdx.x;
    const int lane = tid & 31;
    const int warp = tid >> 5;
    const int wm   = warp & 1;
    const int wn   = warp >> 1;
    const int bx = blockIdx.x;      // b (0..31)
    const int by = blockIdx.y;      // node tile

    const char* aSrc = (const char*)(g_adjb + (size_t)(by * 128) * N_);
    const char* bSrc = (const char*)(g_gT   + (size_t)(bx * 128) * N_);

    float acc[4][4][4];
#pragma unroll
    for (int i = 0; i < 4; i++)
#pragma unroll
        for (int j = 0; j < 4; j++)
#pragma unroll
            for (int v = 0; v < 4; v++) acc[i][j][v] = 0.0f;

    const int ldRow = tid >> 3;
    const int ldCol = tid & 7;

    auto issue = [&](int kt, int s) {
        const uint32_t aB = sb + s * AJ_STAGE_B;
        const uint32_t bB = aB + AJ_TILE;
#pragma unroll
        for (int i = 0; i < 4; i++) {
            const int row = ldRow + 32 * i;
            const uint32_t so = swz((uint32_t)(row * 128 + ldCol * 16));
            const size_t gsrc = (size_t)row * (N_ * 2) + kt * 128 + ldCol * 16;
            cp16(aB + so, aSrc + gsrc);
            cp16(bB + so, bSrc + gsrc);
        }
    };

    auto compute = [&](int s) {
        const uint32_t aB = sb + s * AJ_STAGE_B;
        const uint32_t bB = aB + AJ_TILE;
#pragma unroll
        for (int ks = 0; ks < 4; ks++) {
            const int k0b = ks * 32;
            uint32_t af[4][4], bf[2][4];
#pragma unroll
            for (int mt = 0; mt < 4; mt++) {
                const int row = wm * 64 + mt * 16 + (lane & 15);
                ldsm4(af[mt], aB + swz((uint32_t)(row * 128 + k0b + ((lane >> 4) << 4))));
            }
#pragma unroll
            for (int p = 0; p < 2; p++) {
                const int row = wn * 32 + p * 16 + (lane & 7) + ((lane >> 4) << 3);
                ldsm4(bf[p], bB + swz((uint32_t)(row * 128 + k0b + (((lane >> 3) & 1) << 4))));
            }
#pragma unroll
            for (int mt = 0; mt < 4; mt++)
#pragma unroll
                for (int nt = 0; nt < 4; nt++)
                    mma16816(acc[mt][nt], af[mt], &bf[nt >> 1][(nt & 1) * 2]);
        }
    };

    issue(0, 0);
    asm volatile("cp.async.commit_group;" ::: "memory");
    issue(1, 1);
    asm volatile("cp.async.commit_group;" ::: "memory");
    for (int kt = 0; kt < AJ_NK; kt++) {
        asm volatile("cp.async.wait_group 1;" ::: "memory");
        __syncthreads();
        compute(kt % 3);
        const int f = kt + 2;
        if (f < AJ_NK) issue(f, f % 3);
        asm volatile("cp.async.commit_group;" ::: "memory");
    }

    // fused epilogue: full h update (both halves in one pass)
    const bool secondHalf = (wn >= 2);
#pragma unroll
    for (int mt = 0; mt < 4; mt++) {
        const int node0 = by * 128 + wm * 64 + mt * 16 + (lane >> 2);
#pragma unroll
        for (int nt = 0; nt < 4; nt++) {
            const int d = wn * 32 + nt * 8 + 2 * (lane & 3);
#pragma unroll
            for (int r = 0; r < 2; r++) {
                const int node = node0 + r * 8;
                const float t0 = acc[mt][nt][2 * r + 0];
                const float t1 = acc[mt][nt][2 * r + 1];
                const size_t bn = (size_t)bx * N_ + node;
                const size_t hi = bn * D_ + d;
                float2 hv = *reinterpret_cast<const float2*>(g_h + hi);
                if (!secondHalf) {
                    hv.x += DT_ * tanh_fast(t0);
                    hv.y += DT_ * tanh_fast(t1);
                } else {
                    float2 ev = *reinterpret_cast<const float2*>(
                        eps + bn * HALF_ + (d - HALF_));
                    ev.x = fminf(fmaxf(ev.x, 0.0f), 0.1f);
                    ev.y = fminf(fmaxf(ev.y, 0.0f), 0.1f);
                    hv.x = ev.x * (hv.x + DT_ * tanh_fast(t0));
                    hv.y = ev.y * (hv.y + DT_ * tanh_fast(t1));
                }
                if (WH) {
                    *reinterpret_cast<float2*>(g_h + hi) = hv;
                    *reinterpret_cast<__nv_bfloat162*>(g_hb + hi) =
                        __floats2bfloat162_rn(hv.x, hv.y);
                }
                if (WOUT)
                    *reinterpret_cast<float2*>(out + hi) = hv;
            }
        }
    }
}

// ===========================================================================
extern "C" void kernel_launch(void* const* d_in, const int* /*in_sizes*/,
                              int /*n_in*/, void* d_out, int /*out_size*/)
{
    const float* x   = (const float*)d_in[0];
    const float* hz  = (const float*)d_in[1];
    const float* adj = (const float*)d_in[2];
    const float* W1  = (const float*)d_in[3];
    const float* W2  = (const float*)d_in[4];
    const float* Wa  = (const float*)d_in[5];
    const float* ba  = (const float*)d_in[6];
    const float* Wb  = (const float*)d_in[7];
    const float* bb  = (const float*)d_in[8];
    const float* eps = (const float*)d_in[9];
    float* out = (float*)d_out;

    __half *xh_p, *af_p, *WaT_h, *WaT_l, *WbT_h, *WbT_l;
    __nv_bfloat16 *gT_p;
    cudaGetSymbolAddress((void**)&xh_p, g_xh);
    cudaGetSymbolAddress((void**)&af_p, g_af);
    cudaGetSymbolAddress((void**)&WaT_h, g_WaT_h);
    cudaGetSymbolAddress((void**)&WaT_l, g_WaT_l);
    cudaGetSymbolAddress((void**)&WbT_h, g_WbT_h);
    cudaGetSymbolAddress((void**)&WbT_l, g_WbT_l);
    cudaGetSymbolAddress((void**)&gT_p, g_gT);

    cudaFuncSetAttribute(mlp_mma_k<1>,
                         cudaFuncAttributeMaxDynamicSharedMemorySize, MLP_SMEM);
    cudaFuncSetAttribute(mlp_mma_k<2>,
                         cudaFuncAttributeMaxDynamicSharedMemorySize, MLP_SMEM);
    cudaFuncSetAttribute(gproj_k,
                         cudaFuncAttributeMaxDynamicSharedMemorySize, GP_SMEM);
    cudaFuncSetAttribute((const void*)adj_mma_k<false, true>,
                         cudaFuncAttributeMaxDynamicSharedMemorySize, ADJ_SMEM);
    cudaFuncSetAttribute((const void*)adj_mma_k<true, false>,
                         cudaFuncAttributeMaxDynamicSharedMemorySize, ADJ_SMEM);

    const dim3 blk(256);
    const dim3 adjGrid(2 * N_ / 128, N_ / 128);   // 32 x 16

    cvt_all_k<<<CVT_BLOCKS, blk>>>(x, hz, adj, Wa, Wb, W1, W2);

    mlp_mma_k<1><<<dim3(2, M_ROWS / 128), blk, MLP_SMEM>>>(xh_p, WaT_h, WaT_l, ba);
    mlp_mma_k<2><<<dim3(1, M_ROWS / 128), blk, MLP_SMEM>>>(af_p, WbT_h, WbT_l, bb);

    // iteration 0: out writes skipped (overwritten by iteration 1)
    gproj_k<<<dim3(1, M_ROWS / 128), blk, GP_SMEM>>>(gT_p);
    adj_mma_k<false, true><<<adjGrid, blk, ADJ_SMEM>>>(out, eps);

    // iteration 1: write out; skip dead h/hb stores
    gproj_k<<<dim3(1, M_ROWS / 128), blk, GP_SMEM>>>(gT_p);
    adj_mma_k<true, false><<<adjGrid, blk, ADJ_SMEM>>>(out, eps);
}

// round 15
// speedup vs baseline: 1.0930x; 1.0254x over previous
#include <cuda_runtime.h>
#include <cuda_bf16.h>
#include <cuda_fp16.h>
#include <math.h>
#include <stdint.h>

// Problem constants
static constexpr int B_    = 32;
static constexpr int N_    = 2048;
static constexpr int D_    = 128;
static constexpr int HALF_ = 64;
static constexpr float DT_ = 0.01f;
static constexpr int M_ROWS = B_ * N_;   // 65536

// Scratch (static device globals)
__device__ float         g_h  [M_ROWS * D_];      // h fp32 [B][N][D]
__device__ __nv_bfloat16 g_adjb[N_ * N_];         // adj bf16
__device__ __nv_bfloat16 g_gT [2 * N_ * N_];      // gT [b*128+d][node]
__device__ __half        g_xh [M_ROWS * 256];     // concat(x,hz) fp16
__device__ __half        g_af [M_ROWS * 256];     // relu hidden fp16
__device__ __half        g_WaT_h[256 * 256], g_WaT_l[256 * 256];
__device__ __half        g_WbT_h[128 * 256], g_WbT_l[128 * 256];
__device__ __nv_bfloat16 g_WcT[128 * 128];        // [d][k]: d<64->W1, d>=64->W2

__device__ __forceinline__ float4 ld4(const float* p) {
    return *reinterpret_cast<const float4*>(p);
}
__device__ __forceinline__ uint32_t s2u(const void* p) {
    uint32_t r;
    asm("{ .reg .u64 t; cvta.to.shared.u64 t, %1; cvt.u32.u64 %0, t; }"
        : "=r"(r) : "l"(p));
    return r;
}
__device__ __forceinline__ void cp16(uint32_t d, const void* s) {
    asm volatile("cp.async.cg.shared.global [%0], [%1], 16;" :: "r"(d), "l"(s) : "memory");
}
__device__ __forceinline__ uint32_t swz(uint32_t o)   { return o ^ ((o >> 3) & 0x70); }
__device__ __forceinline__ uint32_t swz64(uint32_t o) { return o ^ ((o >> 3) & 0x30); }
__device__ __forceinline__ float tanh_fast(float x) {
    float y;
    asm("tanh.approx.f32 %0, %1;" : "=f"(y) : "f"(x));
    return y;
}
__device__ __forceinline__ void ldsm4(uint32_t (&r)[4], uint32_t addr) {
    asm volatile("ldmatrix.sync.aligned.m8n8.x4.shared.b16 {%0,%1,%2,%3}, [%4];"
                 : "=r"(r[0]), "=r"(r[1]), "=r"(r[2]), "=r"(r[3]) : "r"(addr));
}
__device__ __forceinline__ void mma16816(float (&c)[4], const uint32_t (&a)[4],
                                         const uint32_t* b) {
    asm volatile(
        "mma.sync.aligned.m16n8k16.row.col.f32.bf16.bf16.f32 "
        "{%0,%1,%2,%3}, {%4,%5,%6,%7}, {%8,%9}, {%0,%1,%2,%3};"
        : "+f"(c[0]), "+f"(c[1]), "+f"(c[2]), "+f"(c[3])
        : "r"(a[0]), "r"(a[1]), "r"(a[2]), "r"(a[3]), "r"(b[0]), "r"(b[1]));
}
__device__ __forceinline__ void mma_f16(float (&c)[4], const uint32_t (&a)[4],
                                        const uint32_t* b) {
    asm volatile(
        "mma.sync.aligned.m16n8k16.row.col.f32.f16.f16.f32 "
        "{%0,%1,%2,%3}, {%4,%5,%6,%7}, {%8,%9}, {%0,%1,%2,%3};"
        : "+f"(c[0]), "+f"(c[1]), "+f"(c[2]), "+f"(c[3])
        : "r"(a[0]), "r"(a[1]), "r"(a[2]), "r"(a[3]), "r"(b[0]), "r"(b[1]));
}
__device__ __forceinline__ void split2h(float v, __half& hi, __half& lo) {
    hi = __float2half_rn(v);
    lo = __float2half_rn(v - __half2float(hi));
}

// ===========================================================================
// Shared gproj tail: assumes the h tile (bf16, SW128, 2 chunks of
// [128 rows x 128B]) has been staged at smem offsets 0 / 16384 and ALL
// threads have passed a __syncthreads() since staging. Loads WcT into
// 32768.., computes g = h @ WcT^T, stores bf16 transposed into gT.
// Warp layout: wm = warp&1 (M 2x64), wn = warp>>1 (N 4x32).
// ===========================================================================
__device__ __forceinline__ void gproj_tail(
    uint32_t sb, char* smem, int b, int n0, int tid, int lane, int warp,
    __nv_bfloat16* __restrict__ gT)
{
    // load WcT (128 rows x 2 chunks x 128B) into 32768..
    {
        const int r = tid >> 1, half = tid & 1;
        const size_t bOff = (size_t)r * 128;
#pragma unroll
        for (int c = 0; c < 2; c++)
#pragma unroll
            for (int j = 0; j < 4; j++) {
                const uint32_t so = swz((uint32_t)(r * 128 + (half * 4 + j) * 16));
                cp16(sb + 32768 + c * 16384 + so,
                     g_WcT + bOff + c * 64 + (half * 4 + j) * 8);
            }
    }
    asm volatile("cp.async.commit_group;" ::: "memory");
    asm volatile("cp.async.wait_group 0;" ::: "memory");
    __syncthreads();

    const int wm = warp & 1;
    const int wn = warp >> 1;
    float acc[4][4][4];
#pragma unroll
    for (int i = 0; i < 4; i++)
#pragma unroll
        for (int j = 0; j < 4; j++)
#pragma unroll
            for (int v = 0; v < 4; v++) acc[i][j][v] = 0.0f;

#pragma unroll
    for (int c = 0; c < 2; c++) {
        const uint32_t aB = sb + c * 16384;
        const uint32_t bB = sb + 32768 + c * 16384;
#pragma unroll
        for (int ks = 0; ks < 4; ks++) {
            const int k0b = ks * 32;
            uint32_t af[4][4], bf[2][4];
#pragma unroll
            for (int mt = 0; mt < 4; mt++) {
                const int row = wm * 64 + mt * 16 + (lane & 15);
                ldsm4(af[mt], aB + swz((uint32_t)(row * 128 + k0b + ((lane >> 4) << 4))));
            }
#pragma unroll
            for (int p = 0; p < 2; p++) {
                const int row = wn * 32 + p * 16 + (lane & 7) + ((lane >> 4) << 3);
                ldsm4(bf[p], bB + swz((uint32_t)(row * 128 + k0b + (((lane >> 3) & 1) << 4))));
            }
#pragma unroll
            for (int mt = 0; mt < 4; mt++)
#pragma unroll
                for (int nt = 0; nt < 4; nt++)
                    mma16816(acc[mt][nt], af[mt], &bf[nt >> 1][(nt & 1) * 2]);
        }
    }
    __syncthreads();

    // stage bf16 then transposed coalesced store
    unsigned short* Ts = reinterpret_cast<unsigned short*>(smem + 65536);
#pragma unroll
    for (int mt = 0; mt < 4; mt++) {
        const int row0 = wm * 64 + mt * 16 + (lane >> 2);
#pragma unroll
        for (int nt = 0; nt < 4; nt++) {
            const int col = wn * 32 + nt * 8 + 2 * (lane & 3);
#pragma unroll
            for (int r = 0; r < 2; r++) {
                const int row = row0 + r * 8;
                __nv_bfloat16 b0 = __float2bfloat16(acc[mt][nt][2 * r + 0]);
                __nv_bfloat16 b1 = __float2bfloat16(acc[mt][nt][2 * r + 1]);
                Ts[row * 132 + col]     = *reinterpret_cast<unsigned short*>(&b0);
                Ts[row * 132 + col + 1] = *reinterpret_cast<unsigned short*>(&b1);
            }
        }
    }
    __syncthreads();

    const int colp = tid & 127;
    const int seg  = tid >> 7;
    __nv_bfloat16* dst = gT + (size_t)(b * 128 + colp) * N_ + n0 + seg * 64;
#pragma unroll
    for (int q = 0; q < 8; q++) {
        const int r0 = seg * 64 + q * 8;
        uint32_t w[4];
#pragma unroll
        for (int p = 0; p < 4; p++) {
            uint32_t lo = Ts[(r0 + 2 * p) * 132 + colp];
            uint32_t hi = Ts[(r0 + 2 * p + 1) * 132 + colp];
            w[p] = lo | (hi << 16);
        }
        *reinterpret_cast<uint4*>(dst + q * 8) = make_uint4(w[0], w[1], w[2], w[3]);
    }
}

// smem footprint of any kernel running gproj_tail
static constexpr int TAIL_SMEM = 65536 + 128 * 132 * 2;   // 99328

// ===========================================================================
// Merged conversion kernel (one launch) — unchanged from R14.
// ===========================================================================
static constexpr int CVT_XH_N  = 4194304;
static constexpr int CVT_ADJ_N = 1048576;
static constexpr int CVT_W_N   = 114688;
static constexpr int CVT_TOTAL = CVT_XH_N + CVT_ADJ_N + CVT_W_N;
static constexpr int CVT_BLOCKS = CVT_TOTAL / 256;

__global__ __launch_bounds__(256) void cvt_all_k(
    const float* __restrict__ x,  const float* __restrict__ hz,
    const float* __restrict__ adj,
    const float* __restrict__ Wa, const float* __restrict__ Wb,
    const float* __restrict__ W1, const float* __restrict__ W2)
{
    const int gi = blockIdx.x * 256 + threadIdx.x;
    if (gi < CVT_XH_N) {
        const bool isHz = gi >= (CVT_XH_N / 2);
        const int j = isHz ? gi - CVT_XH_N / 2 : gi;
        const int row = j >> 5;
        const int c4  = (j & 31) * 4;
        float4 v = ld4((isHz ? hz : x) + (size_t)row * 128 + c4);
        const size_t o = (size_t)row * 256 + (isHz ? 128 : 0) + c4;
        *reinterpret_cast<__half2*>(g_xh + o)     = __floats2half2_rn(v.x, v.y);
        *reinterpret_cast<__half2*>(g_xh + o + 2) = __floats2half2_rn(v.z, v.w);
    } else if (gi < CVT_XH_N + CVT_ADJ_N) {
        const int i = gi - CVT_XH_N;
        float4 v = ld4(adj + (size_t)i * 4);
        *reinterpret_cast<__nv_bfloat162*>(g_adjb + (size_t)i * 4)     =
            __floats2bfloat162_rn(v.x, v.y);
        *reinterpret_cast<__nv_bfloat162*>(g_adjb + (size_t)i * 4 + 2) =
            __floats2bfloat162_rn(v.z, v.w);
    } else {
        const int i = gi - CVT_XH_N - CVT_ADJ_N;
        if (i < 65536) {
            const int n = i >> 8, k = i & 255;
            __half hi, lo;
            split2h(Wa[k * 256 + n], hi, lo);
            g_WaT_h[i] = hi; g_WaT_l[i] = lo;
        } else if (i < 65536 + 32768) {
            const int j = i - 65536;
            const int n = j >> 8, k = j & 255;
            __half hi, lo;
            split2h(Wb[k * 128 + n], hi, lo);
            g_WbT_h[j] = hi; g_WbT_l[j] = lo;
        } else {
            const int j = i - 98304;
            const int d = j >> 7, k = j & 127;
            const float w = (d < 64) ? W1[k * 128 + d] : W2[k * 128 + d];
            g_WcT[j] = __float2bfloat16(w);
        }
    }
}

// ===========================================================================
// MLP GEMM (fp16 2-term split). MODE 1: relu -> g_af.
// MODE 2: tanh -> g_h + FUSED gproj (emits iter-0 gT).
// ===========================================================================
static constexpr int MLP_STG_B = 24576;
static constexpr int MLP1_SMEM = 3 * MLP_STG_B;   // 73728
static constexpr int MLP2_SMEM = TAIL_SMEM;       // 99328
static constexpr int MLP_NK    = 8;

template <int MODE>
__global__ __launch_bounds__(256, 2) void mlp_mma_k(
    const __half* __restrict__ A,
    const __half* __restrict__ Bh, const __half* __restrict__ Bl,
    const float* __restrict__ bias, __nv_bfloat16* __restrict__ gT)
{
    extern __shared__ char smem[];
    const uint32_t sb = s2u(smem);
    const int tid  = threadIdx.x;
    const int lane = tid & 31;
    const int warp = tid >> 5;
    const int wm   = warp & 1;
    const int wn   = warp >> 1;
    const int bx = blockIdx.x;
    const int by = blockIdx.y;

    float acc[4][4][4];
#pragma unroll
    for (int i = 0; i < 4; i++)
#pragma unroll
        for (int j = 0; j < 4; j++)
#pragma unroll
            for (int v = 0; v < 4; v++) acc[i][j][v] = 0.0f;

    const int ldRow  = tid >> 1;
    const int ldHalf = tid & 1;

    auto issue = [&](int c, int s) {
        const uint32_t st = sb + s * MLP_STG_B;
        const size_t aOff = (size_t)(by * 128 + ldRow) * 256 + c * 32;
        const size_t bOff = (size_t)(bx * 128 + ldRow) * 256 + c * 32;
#pragma unroll
        for (int j = 0; j < 2; j++) {
            const int chunk = ldHalf * 2 + j;
            const uint32_t so = swz64((uint32_t)(ldRow * 64 + chunk * 16));
            const int e = chunk * 8;
            cp16(st + so,          A  + aOff + e);
            cp16(st + 8192 + so,   Bh + bOff + e);
            cp16(st + 16384 + so,  Bl + bOff + e);
        }
    };

    auto compute = [&](int s) {
        const uint32_t st = sb + s * MLP_STG_B;
#pragma unroll
        for (int ks = 0; ks < 2; ks++) {
            const int k0b = ks * 32;
            uint32_t ah[4][4];
#pragma unroll
            for (int mt = 0; mt < 4; mt++) {
                const int row = wm * 64 + mt * 16 + (lane & 15);
                const uint32_t o = swz64((uint32_t)(row * 64 + k0b + ((lane >> 4) << 4)));
                ldsm4(ah[mt], st + o);
            }
#pragma unroll
            for (int p = 0; p < 2; p++) {
                uint32_t bh[4], bl[4];
                const int row = wn * 32 + p * 16 + (lane & 7) + ((lane >> 4) << 3);
                const uint32_t o = swz64((uint32_t)(row * 64 + k0b + (((lane >> 3) & 1) << 4)));
                ldsm4(bh, st + 8192 + o);
                ldsm4(bl, st + 16384 + o);
#pragma unroll
                for (int mt = 0; mt < 4; mt++)
#pragma unroll
                    for (int sub = 0; sub < 2; sub++) {
                        const int nt = p * 2 + sub;
                        mma_f16(acc[mt][nt], ah[mt], &bh[sub * 2]);
                        mma_f16(acc[mt][nt], ah[mt], &bl[sub * 2]);
                    }
            }
        }
    };

    issue(0, 0);
    asm volatile("cp.async.commit_group;" ::: "memory");
    issue(1, 1);
    asm volatile("cp.async.commit_group;" ::: "memory");
    for (int kt = 0; kt < MLP_NK; kt++) {
        asm volatile("cp.async.wait_group 1;" ::: "memory");
        __syncthreads();
        compute(kt % 3);
        if (kt + 2 < MLP_NK) issue(kt + 2, (kt + 2) % 3);
        asm volatile("cp.async.commit_group;" ::: "memory");
    }

    if (MODE == 2) __syncthreads();   // A-tile staging overlaps stage 1

#pragma unroll
    for (int mt = 0; mt < 4; mt++) {
        const int row0 = by * 128 + wm * 64 + mt * 16 + (lane >> 2);
#pragma unroll
        for (int nt = 0; nt < 4; nt++) {
            const int col = bx * 128 + wn * 32 + nt * 8 + 2 * (lane & 3);
            const float b0 = bias[col], b1 = bias[col + 1];
#pragma unroll
            for (int r = 0; r < 2; r++) {
                const int row = row0 + r * 8;
                float v0 = acc[mt][nt][2 * r + 0] + b0;
                float v1 = acc[mt][nt][2 * r + 1] + b1;
                if (MODE == 1) {
                    v0 = fmaxf(v0, 0.0f);
                    v1 = fmaxf(v1, 0.0f);
                    const size_t o = (size_t)row * 256 + col;
                    *reinterpret_cast<__half2*>(g_af + o) = __floats2half2_rn(v0, v1);
                } else {
                    v0 = tanhf(v0);
                    v1 = tanhf(v1);
                    const size_t o = (size_t)row * 128 + col;
                    *reinterpret_cast<float2*>(g_h + o) = make_float2(v0, v1);
                    // stage bf16 h tile into smem for fused gproj
                    const int lrow = wm * 64 + mt * 16 + (lane >> 2) + r * 8;
                    const int c = col >> 6;
                    const uint32_t so = swz((uint32_t)(lrow * 128 + (col & 63) * 2));
                    *reinterpret_cast<__nv_bfloat162*>(smem + c * 16384 + so) =
                        __floats2bfloat162_rn(v0, v1);
                }
            }
        }
    }

    if (MODE == 2) {
        __syncthreads();
        gproj_tail(sb, smem, by >> 4, (by & 15) * 128, tid, lane, warp, gT);
    }
}

// ===========================================================================
// adj GEMM (bf16 mma, f32 acc) + full h-update epilogue.
// FUSE: stage updated h and run gproj_tail (emits next iteration's gT).
// CTA 128x128, BK=64, 3-stage cp.async, 2 CTAs/SM. Grid (32,16).
// ===========================================================================
static constexpr int AJ_STAGES  = 3;
static constexpr int AJ_NK      = N_ / 64;         // 32
static constexpr int AJ_TILE    = 16384;
static constexpr int AJ_STAGE_B = 2 * AJ_TILE;
static constexpr int ADJ_SMEM   = TAIL_SMEM;       // 99328 (>= 3 stages 98304)

template <bool FUSE, bool WOUT, bool WH>
__global__ __launch_bounds__(256, 2) void adj_mma_k(
    float* __restrict__ out, const float* __restrict__ eps,
    __nv_bfloat16* __restrict__ gT)
{
    extern __shared__ char smem[];
    const uint32_t sb = s2u(smem);
    const int tid  = threadIdx.x;
    const int lane = tid & 31;
    const int warp = tid >> 5;
    const int wm   = warp & 1;
    const int wn   = warp >> 1;
    const int bx = blockIdx.x;      // b (0..31)
    const int by = blockIdx.y;      // node tile

    const char* aSrc = (const char*)(g_adjb + (size_t)(by * 128) * N_);
    const char* bSrc = (const char*)(g_gT   + (size_t)(bx * 128) * N_);

    float acc[4][4][4];
#pragma unroll
    for (int i = 0; i < 4; i++)
#pragma unroll
        for (int j = 0; j < 4; j++)
#pragma unroll
            for (int v = 0; v < 4; v++) acc[i][j][v] = 0.0f;

    const int ldRow = tid >> 3;
    const int ldCol = tid & 7;

    auto issue = [&](int kt, int s) {
        const uint32_t aB = sb + s * AJ_STAGE_B;
        const uint32_t bB = aB + AJ_TILE;
#pragma unroll
        for (int i = 0; i < 4; i++) {
            const int row = ldRow + 32 * i;
            const uint32_t so = swz((uint32_t)(row * 128 + ldCol * 16));
            const size_t gsrc = (size_t)row * (N_ * 2) + kt * 128 + ldCol * 16;
            cp16(aB + so, aSrc + gsrc);
            cp16(bB + so, bSrc + gsrc);
        }
    };

    auto compute = [&](int s) {
        const uint32_t aB = sb + s * AJ_STAGE_B;
        const uint32_t bB = aB + AJ_TILE;
#pragma unroll
        for (int ks = 0; ks < 4; ks++) {
            const int k0b = ks * 32;
            uint32_t af[4][4], bf[2][4];
#pragma unroll
            for (int mt = 0; mt < 4; mt++) {
                const int row = wm * 64 + mt * 16 + (lane & 15);
                ldsm4(af[mt], aB + swz((uint32_t)(row * 128 + k0b + ((lane >> 4) << 4))));
            }
#pragma unroll
            for (int p = 0; p < 2; p++) {
                const int row = wn * 32 + p * 16 + (lane & 7) + ((lane >> 4) << 3);
                ldsm4(bf[p], bB + swz((uint32_t)(row * 128 + k0b + (((lane >> 3) & 1) << 4))));
            }
#pragma unroll
            for (int mt = 0; mt < 4; mt++)
#pragma unroll
                for (int nt = 0; nt < 4; nt++)
                    mma16816(acc[mt][nt], af[mt], &bf[nt >> 1][(nt & 1) * 2]);
        }
    };

    issue(0, 0);
    asm volatile("cp.async.commit_group;" ::: "memory");
    issue(1, 1);
    asm volatile("cp.async.commit_group;" ::: "memory");
    for (int kt = 0; kt < AJ_NK; kt++) {
        asm volatile("cp.async.wait_group 1;" ::: "memory");
        __syncthreads();
        compute(kt % 3);
        const int f = kt + 2;
        if (f < AJ_NK) issue(f, f % 3);
        asm volatile("cp.async.commit_group;" ::: "memory");
    }

    if (FUSE) __syncthreads();   // protect stage 0 before A-tile staging

    // fused epilogue: full h update (both halves in one pass)
    const bool secondHalf = (wn >= 2);
#pragma unroll
    for (int mt = 0; mt < 4; mt++) {
        const int node0 = by * 128 + wm * 64 + mt * 16 + (lane >> 2);
#pragma unroll
        for (int nt = 0; nt < 4; nt++) {
            const int d = wn * 32 + nt * 8 + 2 * (lane & 3);
#pragma unroll
            for (int r = 0; r < 2; r++) {
                const int node = node0 + r * 8;
                const float t0 = acc[mt][nt][2 * r + 0];
                const float t1 = acc[mt][nt][2 * r + 1];
                const size_t bn = (size_t)bx * N_ + node;
                const size_t hi = bn * D_ + d;
                float2 hv = *reinterpret_cast<const float2*>(g_h + hi);
                if (!secondHalf) {
                    hv.x += DT_ * tanh_fast(t0);
                    hv.y += DT_ * tanh_fast(t1);
                } else {
                    float2 ev = *reinterpret_cast<const float2*>(
                        eps + bn * HALF_ + (d - HALF_));
                    ev.x = fminf(fmaxf(ev.x, 0.0f), 0.1f);
                    ev.y = fminf(fmaxf(ev.y, 0.0f), 0.1f);
                    hv.x = ev.x * (hv.x + DT_ * tanh_fast(t0));
                    hv.y = ev.y * (hv.y + DT_ * tanh_fast(t1));
                }
                if (WH)
                    *reinterpret_cast<float2*>(g_h + hi) = hv;
                if (WOUT)
                    *reinterpret_cast<float2*>(out + hi) = hv;
                if (FUSE) {
                    const int lrow = wm * 64 + mt * 16 + (lane >> 2) + r * 8;
                    const int c = d >> 6;
                    const uint32_t so = swz((uint32_t)(lrow * 128 + (d & 63) * 2));
                    *reinterpret_cast<__nv_bfloat162*>(smem + c * 16384 + so) =
                        __floats2bfloat162_rn(hv.x, hv.y);
                }
            }
        }
    }

    if (FUSE) {
        __syncthreads();
        gproj_tail(sb, smem, bx, by * 128, tid, lane, warp, gT);
    }
}

// ===========================================================================
extern "C" void kernel_launch(void* const* d_in, const int* /*in_sizes*/,
                              int /*n_in*/, void* d_out, int /*out_size*/)
{
    const float* x   = (const float*)d_in[0];
    const float* hz  = (const float*)d_in[1];
    const float* adj = (const float*)d_in[2];
    const float* W1  = (const float*)d_in[3];
    const float* W2  = (const float*)d_in[4];
    const float* Wa  = (const float*)d_in[5];
    const float* ba  = (const float*)d_in[6];
    const float* Wb  = (const float*)d_in[7];
    const float* bb  = (const float*)d_in[8];
    const float* eps = (const float*)d_in[9];
    float* out = (float*)d_out;

    __half *xh_p, *af_p, *WaT_h, *WaT_l, *WbT_h, *WbT_l;
    __nv_bfloat16 *gT_p;
    cudaGetSymbolAddress((void**)&xh_p, g_xh);
    cudaGetSymbolAddress((void**)&af_p, g_af);
    cudaGetSymbolAddress((void**)&WaT_h, g_WaT_h);
    cudaGetSymbolAddress((void**)&WaT_l, g_WaT_l);
    cudaGetSymbolAddress((void**)&WbT_h, g_WbT_h);
    cudaGetSymbolAddress((void**)&WbT_l, g_WbT_l);
    cudaGetSymbolAddress((void**)&gT_p, g_gT);

    cudaFuncSetAttribute(mlp_mma_k<1>,
                         cudaFuncAttributeMaxDynamicSharedMemorySize, MLP1_SMEM);
    cudaFuncSetAttribute(mlp_mma_k<2>,
                         cudaFuncAttributeMaxDynamicSharedMemorySize, MLP2_SMEM);
    cudaFuncSetAttribute((const void*)adj_mma_k<true, false, true>,
                         cudaFuncAttributeMaxDynamicSharedMemorySize, ADJ_SMEM);
    cudaFuncSetAttribute((const void*)adj_mma_k<false, true, false>,
                         cudaFuncAttributeMaxDynamicSharedMemorySize, ADJ_SMEM);

    const dim3 blk(256);
    const dim3 adjGrid(2 * N_ / 128, N_ / 128);   // 32 x 16

    cvt_all_k<<<CVT_BLOCKS, blk>>>(x, hz, adj, Wa, Wb, W1, W2);

    mlp_mma_k<1><<<dim3(2, M_ROWS / 128), blk, MLP1_SMEM>>>(
        xh_p, WaT_h, WaT_l, ba, nullptr);
    // MLP2: h = tanh(...) + fused gproj -> gT for iteration 0
    mlp_mma_k<2><<<dim3(1, M_ROWS / 128), blk, MLP2_SMEM>>>(
        af_p, WbT_h, WbT_l, bb, gT_p);

    // iteration 0: update h, fused gproj -> gT for iteration 1
    adj_mma_k<true, false, true><<<adjGrid, blk, ADJ_SMEM>>>(out, eps, gT_p);
    // iteration 1: write out only
    adj_mma_k<false, true, false><<<adjGrid, blk, ADJ_SMEM>>>(out, eps, gT_p);
}

// round 16
// speedup vs baseline: 1.0983x; 1.0049x over previous
#include <cuda_runtime.h>
#include <cuda_bf16.h>
#include <cuda_fp16.h>
#include <math.h>
#include <stdint.h>

// Problem constants
static constexpr int B_    = 32;
static constexpr int N_    = 2048;
static constexpr int D_    = 128;
static constexpr int HALF_ = 64;
static constexpr float DT_ = 0.01f;
static constexpr int M_ROWS = B_ * N_;   // 65536

// Scratch (static device globals)
__device__ float         g_h  [M_ROWS * D_];      // h fp32 [B][N][D]
__device__ __nv_bfloat16 g_adjb[N_ * N_];         // adj bf16
__device__ __nv_bfloat16 g_gT [2 * N_ * N_];      // gT [b*128+d][node]
__device__ __half        g_xh [M_ROWS * 256];     // concat(x,hz) fp16
__device__ __half        g_af [M_ROWS * 256];     // relu hidden fp16
__device__ __half        g_WaT_h[256 * 256], g_WaT_l[256 * 256];
__device__ __half        g_WbT_h[128 * 256], g_WbT_l[128 * 256];
__device__ __nv_bfloat16 g_WcT[128 * 128];        // [d][k]: d<64->W1, d>=64->W2

__device__ __forceinline__ float4 ld4(const float* p) {
    return *reinterpret_cast<const float4*>(p);
}
__device__ __forceinline__ uint32_t s2u(const void* p) {
    uint32_t r;
    asm("{ .reg .u64 t; cvta.to.shared.u64 t, %1; cvt.u32.u64 %0, t; }"
        : "=r"(r) : "l"(p));
    return r;
}
__device__ __forceinline__ void cp16(uint32_t d, const void* s) {
    asm volatile("cp.async.cg.shared.global [%0], [%1], 16;" :: "r"(d), "l"(s) : "memory");
}
__device__ __forceinline__ uint32_t swz(uint32_t o)   { return o ^ ((o >> 3) & 0x70); }
__device__ __forceinline__ uint32_t swz64(uint32_t o) { return o ^ ((o >> 3) & 0x30); }
__device__ __forceinline__ float tanh_fast(float x) {
    float y;
    asm("tanh.approx.f32 %0, %1;" : "=f"(y) : "f"(x));
    return y;
}
__device__ __forceinline__ void ldsm4(uint32_t (&r)[4], uint32_t addr) {
    asm volatile("ldmatrix.sync.aligned.m8n8.x4.shared.b16 {%0,%1,%2,%3}, [%4];"
                 : "=r"(r[0]), "=r"(r[1]), "=r"(r[2]), "=r"(r[3]) : "r"(addr));
}
__device__ __forceinline__ void mma16816(float (&c)[4], const uint32_t (&a)[4],
                                         const uint32_t* b) {
    asm volatile(
        "mma.sync.aligned.m16n8k16.row.col.f32.bf16.bf16.f32 "
        "{%0,%1,%2,%3}, {%4,%5,%6,%7}, {%8,%9}, {%0,%1,%2,%3};"
        : "+f"(c[0]), "+f"(c[1]), "+f"(c[2]), "+f"(c[3])
        : "r"(a[0]), "r"(a[1]), "r"(a[2]), "r"(a[3]), "r"(b[0]), "r"(b[1]));
}
__device__ __forceinline__ void mma_f16(float (&c)[4], const uint32_t (&a)[4],
                                        const uint32_t* b) {
    asm volatile(
        "mma.sync.aligned.m16n8k16.row.col.f32.f16.f16.f32 "
        "{%0,%1,%2,%3}, {%4,%5,%6,%7}, {%8,%9}, {%0,%1,%2,%3};"
        : "+f"(c[0]), "+f"(c[1]), "+f"(c[2]), "+f"(c[3])
        : "r"(a[0]), "r"(a[1]), "r"(a[2]), "r"(a[3]), "r"(b[0]), "r"(b[1]));
}
__device__ __forceinline__ void split2h(float v, __half& hi, __half& lo) {
    hi = __float2half_rn(v);
    lo = __float2half_rn(v - __half2float(hi));
}

// ===========================================================================
// Fused gproj tail, split into two phases so the WcT load overlaps the
// caller's epilogue:
//   gproj_wct_issue : cp.async WcT into smem [32768, 65536). Call right
//                     after the post-mainloop __syncthreads().
//   gproj_tail_run  : wait + sync, then mma + transposed gT store. Assumes
//                     the h tile (bf16, SW128, chunks at 0 / 16384) has been
//                     staged by the caller's epilogue.
// Warp layout inside: wm = warp&1 (M 2x64), wn = warp>>1 (N 4x32).
// ===========================================================================
__device__ __forceinline__ void gproj_wct_issue(uint32_t sb, int tid)
{
    const int r = tid >> 1, half = tid & 1;
    const size_t bOff = (size_t)r * 128;
#pragma unroll
    for (int c = 0; c < 2; c++)
#pragma unroll
        for (int j = 0; j < 4; j++) {
            const uint32_t so = swz((uint32_t)(r * 128 + (half * 4 + j) * 16));
            cp16(sb + 32768 + c * 16384 + so,
                 g_WcT + bOff + c * 64 + (half * 4 + j) * 8);
        }
    asm volatile("cp.async.commit_group;" ::: "memory");
}

__device__ __forceinline__ void gproj_tail_run(
    uint32_t sb, char* smem, int b, int n0, int tid, int lane, int warp,
    __nv_bfloat16* __restrict__ gT)
{
    asm volatile("cp.async.wait_group 0;" ::: "memory");
    __syncthreads();    // WcT visible + h-staging STS visible across warps

    const int wm = warp & 1;
    const int wn = warp >> 1;
    float acc[4][4][4];
#pragma unroll
    for (int i = 0; i < 4; i++)
#pragma unroll
        for (int j = 0; j < 4; j++)
#pragma unroll
            for (int v = 0; v < 4; v++) acc[i][j][v] = 0.0f;

#pragma unroll
    for (int c = 0; c < 2; c++) {
        const uint32_t aB = sb + c * 16384;
        const uint32_t bB = sb + 32768 + c * 16384;
#pragma unroll
        for (int ks = 0; ks < 4; ks++) {
            const int k0b = ks * 32;
            uint32_t af[4][4], bf[2][4];
#pragma unroll
            for (int mt = 0; mt < 4; mt++) {
                const int row = wm * 64 + mt * 16 + (lane & 15);
                ldsm4(af[mt], aB + swz((uint32_t)(row * 128 + k0b + ((lane >> 4) << 4))));
            }
#pragma unroll
            for (int p = 0; p < 2; p++) {
                const int row = wn * 32 + p * 16 + (lane & 7) + ((lane >> 4) << 3);
                ldsm4(bf[p], bB + swz((uint32_t)(row * 128 + k0b + (((lane >> 3) & 1) << 4))));
            }
#pragma unroll
            for (int mt = 0; mt < 4; mt++)
#pragma unroll
                for (int nt = 0; nt < 4; nt++)
                    mma16816(acc[mt][nt], af[mt], &bf[nt >> 1][(nt & 1) * 2]);
        }
    }
    __syncthreads();

    // stage bf16 then transposed coalesced store
    unsigned short* Ts = reinterpret_cast<unsigned short*>(smem + 65536);
#pragma unroll
    for (int mt = 0; mt < 4; mt++) {
        const int row0 = wm * 64 + mt * 16 + (lane >> 2);
#pragma unroll
        for (int nt = 0; nt < 4; nt++) {
            const int col = wn * 32 + nt * 8 + 2 * (lane & 3);
#pragma unroll
            for (int r = 0; r < 2; r++) {
                const int row = row0 + r * 8;
                __nv_bfloat16 b0 = __float2bfloat16(acc[mt][nt][2 * r + 0]);
                __nv_bfloat16 b1 = __float2bfloat16(acc[mt][nt][2 * r + 1]);
                Ts[row * 132 + col]     = *reinterpret_cast<unsigned short*>(&b0);
                Ts[row * 132 + col + 1] = *reinterpret_cast<unsigned short*>(&b1);
            }
        }
    }
    __syncthreads();

    const int colp = tid & 127;
    const int seg  = tid >> 7;
    __nv_bfloat16* dst = gT + (size_t)(b * 128 + colp) * N_ + n0 + seg * 64;
#pragma unroll
    for (int q = 0; q < 8; q++) {
        const int r0 = seg * 64 + q * 8;
        uint32_t w[4];
#pragma unroll
        for (int p = 0; p < 4; p++) {
            uint32_t lo = Ts[(r0 + 2 * p) * 132 + colp];
            uint32_t hi = Ts[(r0 + 2 * p + 1) * 132 + colp];
            w[p] = lo | (hi << 16);
        }
        *reinterpret_cast<uint4*>(dst + q * 8) = make_uint4(w[0], w[1], w[2], w[3]);
    }
}

static constexpr int TAIL_SMEM = 65536 + 128 * 132 * 2;   // 99328

// ===========================================================================
// Merged conversion kernel (one launch) — unchanged.
// ===========================================================================
static constexpr int CVT_XH_N  = 4194304;
static constexpr int CVT_ADJ_N = 1048576;
static constexpr int CVT_W_N   = 114688;
static constexpr int CVT_TOTAL = CVT_XH_N + CVT_ADJ_N + CVT_W_N;
static constexpr int CVT_BLOCKS = CVT_TOTAL / 256;

__global__ __launch_bounds__(256) void cvt_all_k(
    const float* __restrict__ x,  const float* __restrict__ hz,
    const float* __restrict__ adj,
    const float* __restrict__ Wa, const float* __restrict__ Wb,
    const float* __restrict__ W1, const float* __restrict__ W2)
{
    const int gi = blockIdx.x * 256 + threadIdx.x;
    if (gi < CVT_XH_N) {
        const bool isHz = gi >= (CVT_XH_N / 2);
        const int j = isHz ? gi - CVT_XH_N / 2 : gi;
        const int row = j >> 5;
        const int c4  = (j & 31) * 4;
        float4 v = ld4((isHz ? hz : x) + (size_t)row * 128 + c4);
        const size_t o = (size_t)row * 256 + (isHz ? 128 : 0) + c4;
        *reinterpret_cast<__half2*>(g_xh + o)     = __floats2half2_rn(v.x, v.y);
        *reinterpret_cast<__half2*>(g_xh + o + 2) = __floats2half2_rn(v.z, v.w);
    } else if (gi < CVT_XH_N + CVT_ADJ_N) {
        const int i = gi - CVT_XH_N;
        float4 v = ld4(adj + (size_t)i * 4);
        *reinterpret_cast<__nv_bfloat162*>(g_adjb + (size_t)i * 4)     =
            __floats2bfloat162_rn(v.x, v.y);
        *reinterpret_cast<__nv_bfloat162*>(g_adjb + (size_t)i * 4 + 2) =
            __floats2bfloat162_rn(v.z, v.w);
    } else {
        const int i = gi - CVT_XH_N - CVT_ADJ_N;
        if (i < 65536) {
            const int n = i >> 8, k = i & 255;
            __half hi, lo;
            split2h(Wa[k * 256 + n], hi, lo);
            g_WaT_h[i] = hi; g_WaT_l[i] = lo;
        } else if (i < 65536 + 32768) {
            const int j = i - 65536;
            const int n = j >> 8, k = j & 255;
            __half hi, lo;
            split2h(Wb[k * 128 + n], hi, lo);
            g_WbT_h[j] = hi; g_WbT_l[j] = lo;
        } else {
            const int j = i - 98304;
            const int d = j >> 7, k = j & 127;
            const float w = (d < 64) ? W1[k * 128 + d] : W2[k * 128 + d];
            g_WcT[j] = __float2bfloat16(w);
        }
    }
}

// ===========================================================================
// MLP GEMM (fp16 2-term split). MODE 1: relu -> g_af.
// MODE 2: tanh -> g_h + FUSED gproj (emits iter-0 gT), WcT load overlapped.
// ===========================================================================
static constexpr int MLP_STG_B = 24576;
static constexpr int MLP1_SMEM = 3 * MLP_STG_B;   // 73728
static constexpr int MLP2_SMEM = TAIL_SMEM;       // 99328
static constexpr int MLP_NK    = 8;

template <int MODE>
__global__ __launch_bounds__(256, 2) void mlp_mma_k(
    const __half* __restrict__ A,
    const __half* __restrict__ Bh, const __half* __restrict__ Bl,
    const float* __restrict__ bias, __nv_bfloat16* __restrict__ gT)
{
    extern __shared__ char smem[];
    const uint32_t sb = s2u(smem);
    const int tid  = threadIdx.x;
    const int lane = tid & 31;
    const int warp = tid >> 5;
    const int wm   = warp & 1;
    const int wn   = warp >> 1;
    const int bx = blockIdx.x;
    const int by = blockIdx.y;

    float acc[4][4][4];
#pragma unroll
    for (int i = 0; i < 4; i++)
#pragma unroll
        for (int j = 0; j < 4; j++)
#pragma unroll
            for (int v = 0; v < 4; v++) acc[i][j][v] = 0.0f;

    const int ldRow  = tid >> 1;
    const int ldHalf = tid & 1;

    auto issue = [&](int c, int s) {
        const uint32_t st = sb + s * MLP_STG_B;
        const size_t aOff = (size_t)(by * 128 + ldRow) * 256 + c * 32;
        const size_t bOff = (size_t)(bx * 128 + ldRow) * 256 + c * 32;
#pragma unroll
        for (int j = 0; j < 2; j++) {
            const int chunk = ldHalf * 2 + j;
            const uint32_t so = swz64((uint32_t)(ldRow * 64 + chunk * 16));
            const int e = chunk * 8;
            cp16(st + so,          A  + aOff + e);
            cp16(st + 8192 + so,   Bh + bOff + e);
            cp16(st + 16384 + so,  Bl + bOff + e);
        }
    };

    auto compute = [&](int s) {
        const uint32_t st = sb + s * MLP_STG_B;
#pragma unroll
        for (int ks = 0; ks < 2; ks++) {
            const int k0b = ks * 32;
            uint32_t ah[4][4];
#pragma unroll
            for (int mt = 0; mt < 4; mt++) {
                const int row = wm * 64 + mt * 16 + (lane & 15);
                const uint32_t o = swz64((uint32_t)(row * 64 + k0b + ((lane >> 4) << 4)));
                ldsm4(ah[mt], st + o);
            }
#pragma unroll
            for (int p = 0; p < 2; p++) {
                uint32_t bh[4], bl[4];
                const int row = wn * 32 + p * 16 + (lane & 7) + ((lane >> 4) << 3);
                const uint32_t o = swz64((uint32_t)(row * 64 + k0b + (((lane >> 3) & 1) << 4)));
                ldsm4(bh, st + 8192 + o);
                ldsm4(bl, st + 16384 + o);
#pragma unroll
                for (int mt = 0; mt < 4; mt++)
#pragma unroll
                    for (int sub = 0; sub < 2; sub++) {
                        const int nt = p * 2 + sub;
                        mma_f16(acc[mt][nt], ah[mt], &bh[sub * 2]);
                        mma_f16(acc[mt][nt], ah[mt], &bl[sub * 2]);
                    }
            }
        }
    };

    issue(0, 0);
    asm volatile("cp.async.commit_group;" ::: "memory");
    issue(1, 1);
    asm volatile("cp.async.commit_group;" ::: "memory");
    for (int kt = 0; kt < MLP_NK; kt++) {
        asm volatile("cp.async.wait_group 1;" ::: "memory");
        __syncthreads();
        compute(kt % 3);
        if (kt + 2 < MLP_NK) issue(kt + 2, (kt + 2) % 3);
        asm volatile("cp.async.commit_group;" ::: "memory");
    }

    if (MODE == 2) {
        __syncthreads();              // all stage reads complete
        gproj_wct_issue(sb, tid);     // WcT load overlaps epilogue below
    }

#pragma unroll
    for (int mt = 0; mt < 4; mt++) {
        const int row0 = by * 128 + wm * 64 + mt * 16 + (lane >> 2);
#pragma unroll
        for (int nt = 0; nt < 4; nt++) {
            const int col = bx * 128 + wn * 32 + nt * 8 + 2 * (lane & 3);
            const float b0 = bias[col], b1 = bias[col + 1];
#pragma unroll
            for (int r = 0; r < 2; r++) {
                const int row = row0 + r * 8;
                float v0 = acc[mt][nt][2 * r + 0] + b0;
                float v1 = acc[mt][nt][2 * r + 1] + b1;
                if (MODE == 1) {
                    v0 = fmaxf(v0, 0.0f);
                    v1 = fmaxf(v1, 0.0f);
                    const size_t o = (size_t)row * 256 + col;
                    *reinterpret_cast<__half2*>(g_af + o) = __floats2half2_rn(v0, v1);
                } else {
                    v0 = tanhf(v0);
                    v1 = tanhf(v1);
                    const size_t o = (size_t)row * 128 + col;
                    *reinterpret_cast<float2*>(g_h + o) = make_float2(v0, v1);
                    // stage bf16 h tile into smem for fused gproj
                    const int lrow = wm * 64 + mt * 16 + (lane >> 2) + r * 8;
                    const int c = col >> 6;
                    const uint32_t so = swz((uint32_t)(lrow * 128 + (col & 63) * 2));
                    *reinterpret_cast<__nv_bfloat162*>(smem + c * 16384 + so) =
                        __floats2bfloat162_rn(v0, v1);
                }
            }
        }
    }

    if (MODE == 2)
        gproj_tail_run(sb, smem, by >> 4, (by & 15) * 128, tid, lane, warp, gT);
}

// ===========================================================================
// adj GEMM (bf16 mma, f32 acc) + full h-update epilogue.
// FUSE: stage updated h, WcT load overlapped with epilogue, then gproj tail.
// CTA 128x128, BK=64, 3-stage cp.async, 2 CTAs/SM. Grid (32,16).
// ===========================================================================
static constexpr int AJ_STAGES  = 3;
static constexpr int AJ_NK      = N_ / 64;         // 32
static constexpr int AJ_TILE    = 16384;
static constexpr int AJ_STAGE_B = 2 * AJ_TILE;
static constexpr int ADJ_SMEM   = TAIL_SMEM;       // 99328

template <bool FUSE, bool WOUT, bool WH>
__global__ __launch_bounds__(256, 2) void adj_mma_k(
    float* __restrict__ out, const float* __restrict__ eps,
    __nv_bfloat16* __restrict__ gT)
{
    extern __shared__ char smem[];
    const uint32_t sb = s2u(smem);
    const int tid  = threadIdx.x;
    const int lane = tid & 31;
    const int warp = tid >> 5;
    const int wm   = warp & 1;
    const int wn   = warp >> 1;
    const int bx = blockIdx.x;      // b (0..31)
    const int by = blockIdx.y;      // node tile

    const char* aSrc = (const char*)(g_adjb + (size_t)(by * 128) * N_);
    const char* bSrc = (const char*)(g_gT   + (size_t)(bx * 128) * N_);

    float acc[4][4][4];
#pragma unroll
    for (int i = 0; i < 4; i++)
#pragma unroll
        for (int j = 0; j < 4; j++)
#pragma unroll
            for (int v = 0; v < 4; v++) acc[i][j][v] = 0.0f;

    const int ldRow = tid >> 3;
    const int ldCol = tid & 7;

    auto issue = [&](int kt, int s) {
        const uint32_t aB = sb + s * AJ_STAGE_B;
        const uint32_t bB = aB + AJ_TILE;
#pragma unroll
        for (int i = 0; i < 4; i++) {
            const int row = ldRow + 32 * i;
            const uint32_t so = swz((uint32_t)(row * 128 + ldCol * 16));
            const size_t gsrc = (size_t)row * (N_ * 2) + kt * 128 + ldCol * 16;
            cp16(aB + so, aSrc + gsrc);
            cp16(bB + so, bSrc + gsrc);
        }
    };

    auto compute = [&](int s) {
        const uint32_t aB = sb + s * AJ_STAGE_B;
        const uint32_t bB = aB + AJ_TILE;
#pragma unroll
        for (int ks = 0; ks < 4; ks++) {
            const int k0b = ks * 32;
            uint32_t af[4][4], bf[2][4];
#pragma unroll
            for (int mt = 0; mt < 4; mt++) {
                const int row = wm * 64 + mt * 16 + (lane & 15);
                ldsm4(af[mt], aB + swz((uint32_t)(row * 128 + k0b + ((lane >> 4) << 4))));
            }
#pragma unroll
            for (int p = 0; p < 2; p++) {
                const int row = wn * 32 + p * 16 + (lane & 7) + ((lane >> 4) << 3);
                ldsm4(bf[p], bB + swz((uint32_t)(row * 128 + k0b + (((lane >> 3) & 1) << 4))));
            }
#pragma unroll
            for (int mt = 0; mt < 4; mt++)
#pragma unroll
                for (int nt = 0; nt < 4; nt++)
                    mma16816(acc[mt][nt], af[mt], &bf[nt >> 1][(nt & 1) * 2]);
        }
    };

    issue(0, 0);
    asm volatile("cp.async.commit_group;" ::: "memory");
    issue(1, 1);
    asm volatile("cp.async.commit_group;" ::: "memory");
    for (int kt = 0; kt < AJ_NK; kt++) {
        asm volatile("cp.async.wait_group 1;" ::: "memory");
        __syncthreads();
        compute(kt % 3);
        const int f = kt + 2;
        if (f < AJ_NK) issue(f, f % 3);
        asm volatile("cp.async.commit_group;" ::: "memory");
    }

    if (FUSE) {
        __syncthreads();              // all stage reads complete
        gproj_wct_issue(sb, tid);     // WcT load overlaps epilogue below
    }

    // fused epilogue: full h update (both halves in one pass)
    const bool secondHalf = (wn >= 2);
#pragma unroll
    for (int mt = 0; mt < 4; mt++) {
        const int node0 = by * 128 + wm * 64 + mt * 16 + (lane >> 2);
#pragma unroll
        for (int nt = 0; nt < 4; nt++) {
            const int d = wn * 32 + nt * 8 + 2 * (lane & 3);
#pragma unroll
            for (int r = 0; r < 2; r++) {
                const int node = node0 + r * 8;
                const float t0 = acc[mt][nt][2 * r + 0];
                const float t1 = acc[mt][nt][2 * r + 1];
                const size_t bn = (size_t)bx * N_ + node;
                const size_t hi = bn * D_ + d;
                float2 hv = *reinterpret_cast<const float2*>(g_h + hi);
                if (!secondHalf) {
                    hv.x += DT_ * tanh_fast(t0);
                    hv.y += DT_ * tanh_fast(t1);
                } else {
                    float2 ev = *reinterpret_cast<const float2*>(
                        eps + bn * HALF_ + (d - HALF_));
                    ev.x = fminf(fmaxf(ev.x, 0.0f), 0.1f);
                    ev.y = fminf(fmaxf(ev.y, 0.0f), 0.1f);
                    hv.x = ev.x * (hv.x + DT_ * tanh_fast(t0));
                    hv.y = ev.y * (hv.y + DT_ * tanh_fast(t1));
                }
                if (WH)
                    *reinterpret_cast<float2*>(g_h + hi) = hv;
                if (WOUT)
                    *reinterpret_cast<float2*>(out + hi) = hv;
                if (FUSE) {
                    const int lrow = wm * 64 + mt * 16 + (lane >> 2) + r * 8;
                    const int c = d >> 6;
                    const uint32_t so = swz((uint32_t)(lrow * 128 + (d & 63) * 2));
                    *reinterpret_cast<__nv_bfloat162*>(smem + c * 16384 + so) =
                        __floats2bfloat162_rn(hv.x, hv.y);
                }
            }
        }
    }

    if (FUSE)
        gproj_tail_run(sb, smem, bx, by * 128, tid, lane, warp, gT);
}

// ===========================================================================
extern "C" void kernel_launch(void* const* d_in, const int* /*in_sizes*/,
                              int /*n_in*/, void* d_out, int /*out_size*/)
{
    const float* x   = (const float*)d_in[0];
    const float* hz  = (const float*)d_in[1];
    const float* adj = (const float*)d_in[2];
    const float* W1  = (const float*)d_in[3];
    const float* W2  = (const float*)d_in[4];
    const float* Wa  = (const float*)d_in[5];
    const float* ba  = (const float*)d_in[6];
    const float* Wb  = (const float*)d_in[7];
    const float* bb  = (const float*)d_in[8];
    const float* eps = (const float*)d_in[9];
    float* out = (float*)d_out;

    __half *xh_p, *af_p, *WaT_h, *WaT_l, *WbT_h, *WbT_l;
    __nv_bfloat16 *gT_p;
    cudaGetSymbolAddress((void**)&xh_p, g_xh);
    cudaGetSymbolAddress((void**)&af_p, g_af);
    cudaGetSymbolAddress((void**)&WaT_h, g_WaT_h);
    cudaGetSymbolAddress((void**)&WaT_l, g_WaT_l);
    cudaGetSymbolAddress((void**)&WbT_h, g_WbT_h);
    cudaGetSymbolAddress((void**)&WbT_l, g_WbT_l);
    cudaGetSymbolAddress((void**)&gT_p, g_gT);

    cudaFuncSetAttribute(mlp_mma_k<1>,
                         cudaFuncAttributeMaxDynamicSharedMemorySize, MLP1_SMEM);
    cudaFuncSetAttribute(mlp_mma_k<2>,
                         cudaFuncAttributeMaxDynamicSharedMemorySize, MLP2_SMEM);
    cudaFuncSetAttribute((const void*)adj_mma_k<true, false, true>,
                         cudaFuncAttributeMaxDynamicSharedMemorySize, ADJ_SMEM);
    cudaFuncSetAttribute((const void*)adj_mma_k<false, true, false>,
                         cudaFuncAttributeMaxDynamicSharedMemorySize, ADJ_SMEM);

    const dim3 blk(256);
    const dim3 adjGrid(2 * N_ / 128, N_ / 128);   // 32 x 16

    cvt_all_k<<<CVT_BLOCKS, blk>>>(x, hz, adj, Wa, Wb, W1, W2);

    mlp_mma_k<1><<<dim3(2, M_ROWS / 128), blk, MLP1_SMEM>>>(
        xh_p, WaT_h, WaT_l, ba, nullptr);
    // MLP2: h = tanh(...) + fused gproj -> gT for iteration 0
    mlp_mma_k<2><<<dim3(1, M_ROWS / 128), blk, MLP2_SMEM>>>(
        af_p, WbT_h, WbT_l, bb, gT_p);

    // iteration 0: update h, fused gproj -> gT for iteration 1
    adj_mma_k<true, false, true><<<adjGrid, blk, ADJ_SMEM>>>(out, eps, gT_p);
    // iteration 1: write out only
    adj_mma_k<false, true, false><<<adjGrid, blk, ADJ_SMEM>>>(out, eps, gT_p);
}